// round 5
// baseline (speedup 1.0000x reference)
#include <cuda_runtime.h>
#include <cuda_bf16.h>

// FoldTemporalConvTranspose1d:
//   y[b,co,l] = bias[co] + sum_{k=0..7} sum_{c} W[k*COUT+co, c] * x[b, c, l-k]  (l-k >= 0)
// Shapes: x[8,512,2048] f32, W[4096,512] f32, b[512] f32, out[8,512,2048] f32.
//
// GEMM-with-fold: 128(co) x 128(l) CTA tile, 256 threads, 8x8 register tile,
// CK=8 c-chunk. One x smem strip (width 135, zero-padded left) serves all 8
// shifted taps via a 16-wide register window per thread.

#define CIN   512
#define COUT  512
#define LLEN  2048
#define BATCH 8
#define KW    8

#define TM 128
#define TN 128
#define CK 8
#define WS_STRIDE 132   // co-dim padded: conflict-free writes, 16B-aligned rows
#define XS_STRIDE 136   // 135 valid cols, padded to multiple of 8

__global__ __launch_bounds__(256, 2)
void fold_convT_kernel(const float* __restrict__ x,
                       const float* __restrict__ W,
                       const float* __restrict__ bias,
                       float* __restrict__ out)
{
    __shared__ float Ws[KW * CK * WS_STRIDE];  // [kk][cc][co(128, pad 132)]
    __shared__ float xs[CK * XS_STRIDE];       // [cc][j], j=0..134 -> l = l0 + j - 7

    const int tid = threadIdx.x;
    const int tx  = tid & 15;      // l-fragment selector (16 x 8 = 128)
    const int ty  = tid >> 4;      // co-fragment selector (16 x 8 = 128)
    const int bb  = blockIdx.z;
    const int co0 = blockIdx.y * TM;
    const int l0  = blockIdx.x * TN;

    float acc[8][8];
#pragma unroll
    for (int i = 0; i < 8; ++i)
#pragma unroll
        for (int j = 0; j < 8; ++j) acc[i][j] = 0.0f;

    const float* xb = x + (size_t)bb * CIN * LLEN;

#pragma unroll 1
    for (int c0 = 0; c0 < CIN; c0 += CK) {
        __syncthreads();

        // ---- load x strip: CK rows x 135 cols (global l = l0 + col - 7) ----
#pragma unroll
        for (int r = 0; r < 5; ++r) {
            int idx = tid + r * 256;                 // 0 .. 1279, need < 1088
            if (idx < CK * XS_STRIDE) {
                int cc  = idx / XS_STRIDE;
                int col = idx - cc * XS_STRIDE;
                float v = 0.0f;
                int gl = l0 + col - 7;
                if (col < TN + KW - 1 && gl >= 0)
                    v = xb[(size_t)(c0 + cc) * LLEN + gl];
                xs[idx] = v;
            }
        }

        // ---- load W for all 8 taps: 8(kk) x 128(co) x 8(cc) via float4 ----
#pragma unroll
        for (int r = 0; r < 8; ++r) {
            int e   = tid + r * 256;                 // 0 .. 2047 float4 slots
            int cc4 = e & 1;                         // which half of the 8 c's
            int co  = (e >> 1) & 127;
            int kk  = e >> 8;
            const float4 w = *reinterpret_cast<const float4*>(
                W + (size_t)(kk * COUT + co0 + co) * CIN + c0 + cc4 * 4);
            int cb = cc4 * 4;
            Ws[(kk * CK + cb + 0) * WS_STRIDE + co] = w.x;
            Ws[(kk * CK + cb + 1) * WS_STRIDE + co] = w.y;
            Ws[(kk * CK + cb + 2) * WS_STRIDE + co] = w.z;
            Ws[(kk * CK + cb + 3) * WS_STRIDE + co] = w.w;
        }
        __syncthreads();

        // ---- compute: per cc, one 16-float x window feeds all 8 taps ----
#pragma unroll 1
        for (int cc = 0; cc < CK; ++cc) {
            float bWin[16];
            const float4* bp = reinterpret_cast<const float4*>(
                xs + cc * XS_STRIDE + tx * 8);       // 16B-aligned (stride 136)
            float4 b0 = bp[0], b1 = bp[1], b2 = bp[2], b3 = bp[3];
            bWin[0]  = b0.x; bWin[1]  = b0.y; bWin[2]  = b0.z; bWin[3]  = b0.w;
            bWin[4]  = b1.x; bWin[5]  = b1.y; bWin[6]  = b1.z; bWin[7]  = b1.w;
            bWin[8]  = b2.x; bWin[9]  = b2.y; bWin[10] = b2.z; bWin[11] = b2.w;
            bWin[12] = b3.x; bWin[13] = b3.y; bWin[14] = b3.z; bWin[15] = b3.w;

#pragma unroll
            for (int kk = 0; kk < KW; ++kk) {
                const float4* ap = reinterpret_cast<const float4*>(
                    Ws + (kk * CK + cc) * WS_STRIDE + ty * 8); // stride 132 -> aligned
                float4 a0 = ap[0], a1 = ap[1];
                float a[8];
                a[0] = a0.x; a[1] = a0.y; a[2] = a0.z; a[3] = a0.w;
                a[4] = a1.x; a[5] = a1.y; a[6] = a1.z; a[7] = a1.w;
                const int off = 7 - kk;              // window shift for tap kk
#pragma unroll
                for (int ii = 0; ii < 8; ++ii)
#pragma unroll
                    for (int jj = 0; jj < 8; ++jj)
                        acc[ii][jj] = fmaf(a[ii], bWin[jj + off], acc[ii][jj]);
            }
        }
    }

    // ---- epilogue: add bias, vectorized store ----
#pragma unroll
    for (int ii = 0; ii < 8; ++ii) {
        int co = co0 + ty * 8 + ii;
        float bv = __ldg(bias + co);
        float4 o0, o1;
        o0.x = acc[ii][0] + bv; o0.y = acc[ii][1] + bv;
        o0.z = acc[ii][2] + bv; o0.w = acc[ii][3] + bv;
        o1.x = acc[ii][4] + bv; o1.y = acc[ii][5] + bv;
        o1.z = acc[ii][6] + bv; o1.w = acc[ii][7] + bv;
        float* op = out + ((size_t)bb * COUT + co) * LLEN + l0 + tx * 8;
        *reinterpret_cast<float4*>(op)     = o0;
        *reinterpret_cast<float4*>(op + 4) = o1;
    }
}

extern "C" void kernel_launch(void* const* d_in, const int* in_sizes, int n_in,
                              void* d_out, int out_size) {
    const float* x    = (const float*)d_in[0];   // [8, 512, 2048]
    const float* W    = (const float*)d_in[1];   // [4096, 512]
    const float* bias = (const float*)d_in[2];   // [512]
    float* out        = (float*)d_out;           // [8, 512, 2048]

    dim3 grid(LLEN / TN, COUT / TM, BATCH);      // (16, 4, 8) = 512 CTAs
    dim3 block(256);
    fold_convT_kernel<<<grid, block>>>(x, W, bias, out);
}

// round 8
// speedup vs baseline: 2.3145x; 2.3145x over previous
#include <cuda_runtime.h>
#include <cuda_bf16.h>
#include <cstdint>

// FoldTemporalConvTranspose1d via bf16 split-precision mma.sync HMMA GEMM.
//   y[b,co,l] = bias[co] + sum_{k=0..7} sum_c W[k*512+co,c] * x[b,c,l-k]
// Split: v = hi + lo (both RNE bf16); D = Ah*Bh + Ah*Bl + Al*Bh (fp32 acc).
// tcgen05 unavailable (harness emits compute_103 PTX) -> mma.sync m16n8k16.

#define CIN   512
#define COUT  512
#define LLEN  2048
#define BATCH 8
#define KW    8
#define TM    128
#define TN    128
#define KC    32          // c per chunk
#define NCHUNK (CIN / KC) // 16
#define SR    136         // strip rows (TN + 8)
#define PS    40          // padded smem row stride (bf16 units)

// ---------------- scratch (static device globals; allocation-free) ----------
__device__ __align__(16) __nv_bfloat16 g_Wh[KW * COUT * CIN];      // 4 MB
__device__ __align__(16) __nv_bfloat16 g_Wl[KW * COUT * CIN];      // 4 MB
__device__ __align__(16) __nv_bfloat16 g_xh[BATCH * LLEN * CIN];   // 16 MB [b][l][c]
__device__ __align__(16) __nv_bfloat16 g_xl[BATCH * LLEN * CIN];   // 16 MB [b][l][c]

// ---------------- helpers ----------------------------------------------------
__device__ __forceinline__ uint32_t smem_u32(const void* p) {
    uint32_t a;
    asm("{ .reg .u64 t; cvta.to.shared.u64 t, %1; cvt.u32.u64 %0, t; }"
        : "=r"(a) : "l"(p));
    return a;
}

__device__ __forceinline__ void ldmatrix_x4(uint32_t* r, uint32_t addr) {
    asm volatile("ldmatrix.sync.aligned.m8n8.x4.shared.b16 {%0,%1,%2,%3}, [%4];"
                 : "=r"(r[0]), "=r"(r[1]), "=r"(r[2]), "=r"(r[3]) : "r"(addr));
}

__device__ __forceinline__ void mma16816(float* d, const uint32_t* a,
                                         uint32_t b0, uint32_t b1) {
    asm volatile(
        "mma.sync.aligned.m16n8k16.row.col.f32.bf16.bf16.f32 "
        "{%0,%1,%2,%3}, {%4,%5,%6,%7}, {%8,%9}, {%0,%1,%2,%3};"
        : "+f"(d[0]), "+f"(d[1]), "+f"(d[2]), "+f"(d[3])
        : "r"(a[0]), "r"(a[1]), "r"(a[2]), "r"(a[3]), "r"(b0), "r"(b1));
}

__device__ __forceinline__ uint32_t pack2(__nv_bfloat16 a, __nv_bfloat16 b) {
    uint16_t ua = *reinterpret_cast<uint16_t*>(&a);
    uint16_t ub = *reinterpret_cast<uint16_t*>(&b);
    return (uint32_t)ua | ((uint32_t)ub << 16);    // a in low half (element 0)
}

// ---------------- pre-pass: W -> Wh/Wl ---------------------------------------
__global__ __launch_bounds__(256)
void convert_w(const float* __restrict__ W) {
    int i = blockIdx.x * 256 + threadIdx.x;          // over float4s
    float4 v = reinterpret_cast<const float4*>(W)[i];
    __nv_bfloat16 h0 = __float2bfloat16_rn(v.x);
    __nv_bfloat16 h1 = __float2bfloat16_rn(v.y);
    __nv_bfloat16 h2 = __float2bfloat16_rn(v.z);
    __nv_bfloat16 h3 = __float2bfloat16_rn(v.w);
    __nv_bfloat16 l0 = __float2bfloat16_rn(v.x - __bfloat162float(h0));
    __nv_bfloat16 l1 = __float2bfloat16_rn(v.y - __bfloat162float(h1));
    __nv_bfloat16 l2 = __float2bfloat16_rn(v.z - __bfloat162float(h2));
    __nv_bfloat16 l3 = __float2bfloat16_rn(v.w - __bfloat162float(h3));
    reinterpret_cast<uint2*>(g_Wh)[i] = make_uint2(pack2(h0, h1), pack2(h2, h3));
    reinterpret_cast<uint2*>(g_Wl)[i] = make_uint2(pack2(l0, l1), pack2(l2, l3));
}

// ---------------- pre-pass: x -> transposed xh/xl [b][l][c] -------------------
__global__ __launch_bounds__(256)
void convert_x(const float* __restrict__ x) {
    __shared__ float t[32][33];
    const int tx = threadIdx.x, ty = threadIdx.y;
    const int lbase = blockIdx.x * 32;
    const int cbase = blockIdx.y * 32;
    const int b = blockIdx.z;

#pragma unroll
    for (int r = 0; r < 4; ++r) {
        int c = cbase + ty + r * 8;
        t[ty + r * 8][tx] = x[((size_t)b * CIN + c) * LLEN + lbase + tx];
    }
    __syncthreads();
#pragma unroll
    for (int r = 0; r < 4; ++r) {
        int l = lbase + ty + r * 8;
        float v = t[tx][ty + r * 8];
        __nv_bfloat16 h = __float2bfloat16_rn(v);
        __nv_bfloat16 lo = __float2bfloat16_rn(v - __bfloat162float(h));
        size_t o = ((size_t)b * LLEN + l) * CIN + cbase + tx;
        g_xh[o] = h;
        g_xl[o] = lo;
    }
}

// ---------------- main GEMM ---------------------------------------------------
__global__ __launch_bounds__(256, 2)
void fold_convT_mma(const float* __restrict__ bias, float* __restrict__ out)
{
    __shared__ __align__(16) uint16_t sA[2][TM * PS];  // [hi/lo][128 x 40]
    __shared__ __align__(16) uint16_t sB[2][SR * PS];  // [hi/lo][136 x 40]

    const int tid  = threadIdx.x;
    const int lane = tid & 31;
    const int wid  = tid >> 5;
    const int wm   = wid >> 2;        // 0..1 -> co 64-block
    const int wn   = wid & 3;         // 0..3 -> l 32-block
    const int bb   = blockIdx.z;
    const int co0  = blockIdx.y * TM;
    const int l0   = blockIdx.x * TN;

    float acc[4][4][4];
#pragma unroll
    for (int i = 0; i < 4; ++i)
#pragma unroll
        for (int j = 0; j < 4; ++j)
#pragma unroll
            for (int q = 0; q < 4; ++q) acc[i][j][q] = 0.0f;

    // per-thread ldmatrix-A base (bf16-element offset; bytes at use site)
    const int a_elt = (wm * 64 + (lane & 15)) * PS + (lane >> 4) * 8;
    const uint32_t sAh_u = smem_u32(sA[0]);
    const uint32_t sAl_u = smem_u32(sA[1]);

    // A tile loader: 256 threads, each one 16-element half-row (2 x uint4)
    const int arow  = tid >> 1;
    const int ahalf = (tid & 1) * 16;

#pragma unroll 1
    for (int ci = 0; ci < NCHUNK; ++ci) {
        const int c0 = ci * KC;

        // ---- load x strip (hi/lo): 136 rows x 32 c, as 4 x 8-elt uint4 slots ----
        __syncthreads();   // previous chunk's compute done before overwrite
#pragma unroll
        for (int e = tid; e < SR * 4; e += 256) {
            int s = e >> 2;                 // strip row: l = l0 + s - 7
            int q = (e & 3) * 8;            // 8-element column slot
            int l = l0 + s - 7;
            uint4 vh = make_uint4(0, 0, 0, 0), vl = make_uint4(0, 0, 0, 0);
            if (l >= 0 && l < LLEN) {
                size_t o = ((size_t)bb * LLEN + l) * CIN + c0 + q;
                vh = *reinterpret_cast<const uint4*>(g_xh + o);
                vl = *reinterpret_cast<const uint4*>(g_xl + o);
            }
            *reinterpret_cast<uint4*>(sB[0] + s * PS + q) = vh;
            *reinterpret_cast<uint4*>(sB[1] + s * PS + q) = vl;
        }

#pragma unroll 1
        for (int tap = 0; tap < KW; ++tap) {
            __syncthreads();   // previous tap compute done; strip ready (tap 0)

            // ---- load W tiles (hi/lo) for this tap ----
            {
                size_t o = ((size_t)(tap * COUT + co0 + arow)) * CIN + c0 + ahalf;
                const uint4* gh = reinterpret_cast<const uint4*>(g_Wh + o);
                const uint4* gl = reinterpret_cast<const uint4*>(g_Wl + o);
                uint4* dh = reinterpret_cast<uint4*>(sA[0] + arow * PS + ahalf);
                uint4* dl = reinterpret_cast<uint4*>(sA[1] + arow * PS + ahalf);
                dh[0] = gh[0]; dh[1] = gh[1];
                dl[0] = gl[0]; dl[1] = gl[1];
            }
            __syncthreads();

            // ---- compute: 2 k16-steps x 3 split terms x 16 mma ----
            const int bidx0 = (wn * 32 + (lane >> 2) + 7 - tap) * PS + (lane & 3) * 2;
            const uint16_t* sBh = sB[0];
            const uint16_t* sBl = sB[1];

#pragma unroll
            for (int ks = 0; ks < 2; ++ks) {
                uint32_t Bh[8], Bl[8];
#pragma unroll
                for (int nf = 0; nf < 4; ++nf) {
                    int idx = bidx0 + nf * (8 * PS) + ks * 16;
                    Bh[nf * 2 + 0] = *reinterpret_cast<const uint32_t*>(sBh + idx);
                    Bh[nf * 2 + 1] = *reinterpret_cast<const uint32_t*>(sBh + idx + 8);
                    Bl[nf * 2 + 0] = *reinterpret_cast<const uint32_t*>(sBl + idx);
                    Bl[nf * 2 + 1] = *reinterpret_cast<const uint32_t*>(sBl + idx + 8);
                }

                uint32_t a[4][4];
                const uint32_t abyte = (uint32_t)(a_elt + ks * 16) * 2;
#pragma unroll
                for (int mf = 0; mf < 4; ++mf)
                    ldmatrix_x4(a[mf], sAh_u + abyte + mf * (16 * PS * 2));

                // hh + hl
#pragma unroll
                for (int mf = 0; mf < 4; ++mf)
#pragma unroll
                    for (int nf = 0; nf < 4; ++nf)
                        mma16816(acc[mf][nf], a[mf], Bh[nf * 2], Bh[nf * 2 + 1]);
#pragma unroll
                for (int mf = 0; mf < 4; ++mf)
#pragma unroll
                    for (int nf = 0; nf < 4; ++nf)
                        mma16816(acc[mf][nf], a[mf], Bl[nf * 2], Bl[nf * 2 + 1]);

                // lh (Al x Bh), overwrite A frags
#pragma unroll
                for (int mf = 0; mf < 4; ++mf)
                    ldmatrix_x4(a[mf], sAl_u + abyte + mf * (16 * PS * 2));
#pragma unroll
                for (int mf = 0; mf < 4; ++mf)
#pragma unroll
                    for (int nf = 0; nf < 4; ++nf)
                        mma16816(acc[mf][nf], a[mf], Bh[nf * 2], Bh[nf * 2 + 1]);
            }
        }
    }

    // ---- epilogue: add bias, store float2 per (row, 8-col frag) ----
    const int r  = lane >> 2;
    const int cq = (lane & 3) * 2;
#pragma unroll
    for (int mf = 0; mf < 4; ++mf) {
#pragma unroll
        for (int h2 = 0; h2 < 2; ++h2) {
            int row = co0 + wm * 64 + mf * 16 + h2 * 8 + r;
            float bv = __ldg(bias + row);
            float* orow = out + ((size_t)bb * COUT + row) * LLEN + l0 + wn * 32 + cq;
#pragma unroll
            for (int nf = 0; nf < 4; ++nf) {
                float2 v;
                v.x = acc[mf][nf][h2 * 2 + 0] + bv;
                v.y = acc[mf][nf][h2 * 2 + 1] + bv;
                *reinterpret_cast<float2*>(orow + nf * 8) = v;
            }
        }
    }
}

extern "C" void kernel_launch(void* const* d_in, const int* in_sizes, int n_in,
                              void* d_out, int out_size) {
    const float* x    = (const float*)d_in[0];   // [8, 512, 2048]
    const float* W    = (const float*)d_in[1];   // [4096, 512]
    const float* bias = (const float*)d_in[2];   // [512]
    float* out        = (float*)d_out;           // [8, 512, 2048]

    // pre-pass conversions (same stream; graph-capturable)
    convert_w<<<(KW * COUT * CIN / 4) / 256, 256>>>(W);
    {
        dim3 g(LLEN / 32, CIN / 32, BATCH);
        dim3 b(32, 8);
        convert_x<<<g, b>>>(x);
    }

    dim3 grid(LLEN / TN, COUT / TM, BATCH);      // (16, 4, 8) = 512 CTAs
    fold_convT_mma<<<grid, 256>>>(bias, out);
}

// round 9
// speedup vs baseline: 2.4995x; 1.0800x over previous
#include <cuda_runtime.h>
#include <cuda_bf16.h>
#include <cstdint>

// FoldTemporalConvTranspose1d via bf16 split-precision mma.sync HMMA GEMM.
//   y[b,co,l] = bias[co] + sum_{k=0..7} sum_c W[k*512+co,c] * x[b,c,l-k]
// Split: v = hi + lo (both RNE bf16); D = Ah*Bh + Ah*Bl + Al*Bh (fp32 acc).
// R8: cp.async double-buffered W tile + x strip (1 sync/iter, latency hidden),
//     B fragments via ldmatrix.x4 (conflict-free) instead of scalar LDS.

#define CIN   512
#define COUT  512
#define LLEN  2048
#define BATCH 8
#define KW    8
#define TM    128
#define TN    128
#define KC    32
#define NCHUNK (CIN / KC)   // 16
#define NIT   (NCHUNK * KW) // 128
#define SR    136           // strip rows
#define PS    40            // padded smem row stride (bf16 units)

// smem layout (bytes, dynamic)
#define SA_HL   10240                 // 128 * 40 * 2
#define SA_ST   (2 * SA_HL)           // hi + lo
#define SB_BASE (2 * SA_ST)           // 40960
#define SB_HL   10880                 // 136 * 40 * 2
#define SB_ST   (2 * SB_HL)
#define SMEM_TOTAL (SB_BASE + 2 * SB_ST)  // 84480

// ---------------- scratch (static device globals; allocation-free) ----------
__device__ __align__(16) __nv_bfloat16 g_Wh[KW * COUT * CIN];
__device__ __align__(16) __nv_bfloat16 g_Wl[KW * COUT * CIN];
__device__ __align__(16) __nv_bfloat16 g_xh[BATCH * LLEN * CIN];  // [b][l][c]
__device__ __align__(16) __nv_bfloat16 g_xl[BATCH * LLEN * CIN];  // [b][l][c]

// ---------------- helpers ----------------------------------------------------
__device__ __forceinline__ uint32_t smem_u32(const void* p) {
    uint32_t a;
    asm("{ .reg .u64 t; cvta.to.shared.u64 t, %1; cvt.u32.u64 %0, t; }"
        : "=r"(a) : "l"(p));
    return a;
}
__device__ __forceinline__ void ldmatrix_x4(uint32_t* r, uint32_t addr) {
    asm volatile("ldmatrix.sync.aligned.m8n8.x4.shared.b16 {%0,%1,%2,%3}, [%4];"
                 : "=r"(r[0]), "=r"(r[1]), "=r"(r[2]), "=r"(r[3]) : "r"(addr));
}
__device__ __forceinline__ void mma16816(float* d, const uint32_t* a,
                                         uint32_t b0, uint32_t b1) {
    asm volatile(
        "mma.sync.aligned.m16n8k16.row.col.f32.bf16.bf16.f32 "
        "{%0,%1,%2,%3}, {%4,%5,%6,%7}, {%8,%9}, {%0,%1,%2,%3};"
        : "+f"(d[0]), "+f"(d[1]), "+f"(d[2]), "+f"(d[3])
        : "r"(a[0]), "r"(a[1]), "r"(a[2]), "r"(a[3]), "r"(b0), "r"(b1));
}
__device__ __forceinline__ void cpa16(uint32_t dst, const void* src) {
    asm volatile(
        "{ .reg .u64 g; cvta.to.global.u64 g, %1;"
        " cp.async.cg.shared.global [%0], [g], 16; }"
        :: "r"(dst), "l"(src) : "memory");
}
__device__ __forceinline__ void cpa16z(uint32_t dst, const void* src, bool p) {
    int sz = p ? 16 : 0;
    asm volatile(
        "{ .reg .u64 g; cvta.to.global.u64 g, %1;"
        " cp.async.cg.shared.global [%0], [g], 16, %2; }"
        :: "r"(dst), "l"(src), "r"(sz) : "memory");
}
__device__ __forceinline__ void cpa_commit() {
    asm volatile("cp.async.commit_group;" ::: "memory");
}
template <int N>
__device__ __forceinline__ void cpa_wait() {
    asm volatile("cp.async.wait_group %0;" :: "n"(N) : "memory");
}
__device__ __forceinline__ uint32_t pack2(__nv_bfloat16 a, __nv_bfloat16 b) {
    uint16_t ua = *reinterpret_cast<uint16_t*>(&a);
    uint16_t ub = *reinterpret_cast<uint16_t*>(&b);
    return (uint32_t)ua | ((uint32_t)ub << 16);
}

// ---------------- pre-pass: W -> Wh/Wl ---------------------------------------
__global__ __launch_bounds__(256)
void convert_w(const float* __restrict__ W) {
    int i = blockIdx.x * 256 + threadIdx.x;
    float4 v = reinterpret_cast<const float4*>(W)[i];
    __nv_bfloat16 h0 = __float2bfloat16_rn(v.x);
    __nv_bfloat16 h1 = __float2bfloat16_rn(v.y);
    __nv_bfloat16 h2 = __float2bfloat16_rn(v.z);
    __nv_bfloat16 h3 = __float2bfloat16_rn(v.w);
    __nv_bfloat16 l0 = __float2bfloat16_rn(v.x - __bfloat162float(h0));
    __nv_bfloat16 l1 = __float2bfloat16_rn(v.y - __bfloat162float(h1));
    __nv_bfloat16 l2 = __float2bfloat16_rn(v.z - __bfloat162float(h2));
    __nv_bfloat16 l3 = __float2bfloat16_rn(v.w - __bfloat162float(h3));
    reinterpret_cast<uint2*>(g_Wh)[i] = make_uint2(pack2(h0, h1), pack2(h2, h3));
    reinterpret_cast<uint2*>(g_Wl)[i] = make_uint2(pack2(l0, l1), pack2(l2, l3));
}

// ---------------- pre-pass: x -> transposed xh/xl [b][l][c] -------------------
__global__ __launch_bounds__(256)
void convert_x(const float* __restrict__ x) {
    __shared__ float t[32][33];
    const int tx = threadIdx.x, ty = threadIdx.y;
    const int lbase = blockIdx.x * 32;
    const int cbase = blockIdx.y * 32;
    const int b = blockIdx.z;
#pragma unroll
    for (int r = 0; r < 4; ++r) {
        int c = cbase + ty + r * 8;
        t[ty + r * 8][tx] = x[((size_t)b * CIN + c) * LLEN + lbase + tx];
    }
    __syncthreads();
#pragma unroll
    for (int r = 0; r < 4; ++r) {
        int l = lbase + ty + r * 8;
        float v = t[tx][ty + r * 8];
        __nv_bfloat16 h = __float2bfloat16_rn(v);
        __nv_bfloat16 lo = __float2bfloat16_rn(v - __bfloat162float(h));
        size_t o = ((size_t)b * LLEN + l) * CIN + cbase + tx;
        g_xh[o] = h;
        g_xl[o] = lo;
    }
}

// ---------------- main GEMM ---------------------------------------------------
__global__ __launch_bounds__(256, 2)
void fold_convT_mma(const float* __restrict__ bias, float* __restrict__ out)
{
    extern __shared__ char smem[];
    const uint32_t sbase = smem_u32(smem);

    const int tid  = threadIdx.x;
    const int lane = tid & 31;
    const int wid  = tid >> 5;
    const int wm   = wid >> 2;
    const int wn   = wid & 3;
    const int bb   = blockIdx.z;
    const int co0  = blockIdx.y * TM;
    const int l0   = blockIdx.x * TN;

    float acc[4][4][4];
#pragma unroll
    for (int i = 0; i < 4; ++i)
#pragma unroll
        for (int j = 0; j < 4; ++j)
#pragma unroll
            for (int q = 0; q < 4; ++q) acc[i][j][q] = 0.0f;

    // ldmatrix-A per-lane element offset within a stage
    const int a_elt = (wm * 64 + (lane & 15)) * PS + (lane >> 4) * 8;
    // ldmatrix-B per-lane element offset: matrix idx = lane>>3
    //   rows 0-7 / 8-15 per 16-n block, col half 0/8
    const int b_lane = ((lane & 7) + ((lane >> 4) << 3)) * PS + ((lane >> 3) & 1) * 8;

    // W loader: each thread owns one 16-elem half-row (2 x 16B)
    const int arow  = tid >> 1;
    const int ahalf = (tid & 1) * 16;

    // ---- prefetch issue helpers ----
    auto issue_W = [&](int it, int stage) {
        const int ci  = it >> 3;
        const int tap = it & 7;
        const size_t o = ((size_t)(tap * COUT + co0 + arow)) * CIN
                         + ci * KC + ahalf;
        const uint32_t dh = sbase + stage * SA_ST + (arow * PS + ahalf) * 2;
        const uint32_t dl = dh + SA_HL;
        cpa16(dh,      g_Wh + o);
        cpa16(dh + 16, g_Wh + o + 8);
        cpa16(dl,      g_Wl + o);
        cpa16(dl + 16, g_Wl + o + 8);
    };
    auto issue_strip = [&](int ci, int stage) {
        const int c0 = ci * KC;
        const uint32_t bh = sbase + SB_BASE + stage * SB_ST;
#pragma unroll
        for (int e = tid; e < SR * 4; e += 256) {
            int s = e >> 2;
            int q = (e & 3) * 8;
            int l = l0 + s - 7;
            bool p = (l >= 0) && (l < LLEN);
            int lc = p ? l : 0;
            size_t o = ((size_t)bb * LLEN + lc) * CIN + c0 + q;
            uint32_t d = bh + (s * PS + q) * 2;
            cpa16z(d,         g_xh + o, p);
            cpa16z(d + SB_HL, g_xl + o, p);
        }
    };

    // ---- prologue: strip(chunk 0) + W(it 0) into stage 0 ----
    issue_strip(0, 0);
    issue_W(0, 0);
    cpa_commit();

#pragma unroll 1
    for (int it = 0; it < NIT; ++it) {
        const int ci  = it >> 3;
        const int tap = it & 7;

        cpa_wait<0>();        // data(it) copies done (own thread)
        __syncthreads();      // visible to all; all warps done compute(it-1)

        if (it < NIT - 1) {   // prefetch it+1 (overlaps compute below)
            issue_W(it + 1, (it + 1) & 1);
            if (tap == 7) issue_strip(ci + 1, (ci + 1) & 1);
            cpa_commit();
        }

        const uint32_t sAh_u = sbase + (it & 1) * SA_ST;
        const uint32_t sAl_u = sAh_u + SA_HL;
        const uint32_t sBh_u = sbase + SB_BASE + (ci & 1) * SB_ST;
        const uint32_t sBl_u = sBh_u + SB_HL;
        const int rowOff = (wn * 32 + 7 - tap) * PS;

#pragma unroll
        for (int ks = 0; ks < 2; ++ks) {
            // B fragments via ldmatrix.x4 (no trans: sB is [n][k] row-major)
            uint32_t Bh[8], Bl[8];
#pragma unroll
            for (int nfp = 0; nfp < 2; ++nfp) {
                uint32_t eb = (uint32_t)(b_lane + rowOff + nfp * 16 * PS
                                         + ks * 16) * 2;
                ldmatrix_x4(&Bh[nfp * 4], sBh_u + eb);
                ldmatrix_x4(&Bl[nfp * 4], sBl_u + eb);
            }

            uint32_t a[4][4];
            const uint32_t abyte = (uint32_t)(a_elt + ks * 16) * 2;
#pragma unroll
            for (int mf = 0; mf < 4; ++mf)
                ldmatrix_x4(a[mf], sAh_u + abyte + mf * (16 * PS * 2));

            // hh
#pragma unroll
            for (int mf = 0; mf < 4; ++mf)
#pragma unroll
                for (int nf = 0; nf < 4; ++nf)
                    mma16816(acc[mf][nf], a[mf], Bh[nf * 2], Bh[nf * 2 + 1]);
            // hl
#pragma unroll
            for (int mf = 0; mf < 4; ++mf)
#pragma unroll
                for (int nf = 0; nf < 4; ++nf)
                    mma16816(acc[mf][nf], a[mf], Bl[nf * 2], Bl[nf * 2 + 1]);
            // lh (overwrite A frags with Al)
#pragma unroll
            for (int mf = 0; mf < 4; ++mf)
                ldmatrix_x4(a[mf], sAl_u + abyte + mf * (16 * PS * 2));
#pragma unroll
            for (int mf = 0; mf < 4; ++mf)
#pragma unroll
                for (int nf = 0; nf < 4; ++nf)
                    mma16816(acc[mf][nf], a[mf], Bh[nf * 2], Bh[nf * 2 + 1]);
        }
    }

    // ---- epilogue: add bias, store float2 per (row, 8-col frag) ----
    const int r  = lane >> 2;
    const int cq = (lane & 3) * 2;
#pragma unroll
    for (int mf = 0; mf < 4; ++mf) {
#pragma unroll
        for (int h2 = 0; h2 < 2; ++h2) {
            int row = co0 + wm * 64 + mf * 16 + h2 * 8 + r;
            float bv = __ldg(bias + row);
            float* orow = out + ((size_t)bb * COUT + row) * LLEN + l0 + wn * 32 + cq;
#pragma unroll
            for (int nf = 0; nf < 4; ++nf) {
                float2 v;
                v.x = acc[mf][nf][h2 * 2 + 0] + bv;
                v.y = acc[mf][nf][h2 * 2 + 1] + bv;
                *reinterpret_cast<float2*>(orow + nf * 8) = v;
            }
        }
    }
}

extern "C" void kernel_launch(void* const* d_in, const int* in_sizes, int n_in,
                              void* d_out, int out_size) {
    const float* x    = (const float*)d_in[0];   // [8, 512, 2048]
    const float* W    = (const float*)d_in[1];   // [4096, 512]
    const float* bias = (const float*)d_in[2];   // [512]
    float* out        = (float*)d_out;           // [8, 512, 2048]

    convert_w<<<(KW * COUT * CIN / 4) / 256, 256>>>(W);
    {
        dim3 g(LLEN / 32, CIN / 32, BATCH);
        dim3 b(32, 8);
        convert_x<<<g, b>>>(x);
    }

    cudaFuncSetAttribute(fold_convT_mma,
                         cudaFuncAttributeMaxDynamicSharedMemorySize, SMEM_TOTAL);
    dim3 grid(LLEN / TN, COUT / TM, BATCH);      // (16, 4, 8) = 512 CTAs
    fold_convT_mma<<<grid, 256, SMEM_TOTAL>>>(bias, out);
}

// round 10
// speedup vs baseline: 3.9303x; 1.5724x over previous
#include <cuda_runtime.h>
#include <cuda_fp16.h>
#include <cstdint>

// FoldTemporalConvTranspose1d via fp16 split-precision mma.sync HMMA GEMM.
//   y[b,co,l] = bias[co] + sum_{k=0..7} sum_c W[k*512+co,c] * x[b,c,l-k]
// R9 precision plan: x = Xh + Xl (fp16 RNE split), W = single fp16 RNE.
//   D = W*Xh + W*Xl  (fp32 acc)  -> 2 MMA terms (was 3 with bf16 split).
// Error ~ 2^-11/sqrt(3) from W quantization ≈ 2.8e-4 << 1e-3.

#define CIN   512
#define COUT  512
#define LLEN  2048
#define BATCH 8
#define KW    8
#define TM    128
#define TN    128
#define KC    32
#define NCHUNK (CIN / KC)   // 16
#define NIT   (NCHUNK * KW) // 128
#define SR    136           // strip rows
#define PS    40            // padded smem row stride (fp16 units)

// smem layout (bytes, dynamic)
#define SA_ST   10240                 // 128 * 40 * 2 (W single, per stage)
#define SB_BASE (2 * SA_ST)           // 20480
#define SB_HL   10880                 // 136 * 40 * 2
#define SB_ST   (2 * SB_HL)           // hi + lo
#define SMEM_TOTAL (SB_BASE + 2 * SB_ST)  // 64000

// ---------------- scratch (static device globals; allocation-free) ----------
__device__ __align__(16) __half g_Wf[KW * COUT * CIN];           // 4 MB
__device__ __align__(16) __half g_xh[BATCH * LLEN * CIN];        // 16 MB [b][l][c]
__device__ __align__(16) __half g_xl[BATCH * LLEN * CIN];        // 16 MB [b][l][c]

// ---------------- helpers ----------------------------------------------------
__device__ __forceinline__ uint32_t smem_u32(const void* p) {
    uint32_t a;
    asm("{ .reg .u64 t; cvta.to.shared.u64 t, %1; cvt.u32.u64 %0, t; }"
        : "=r"(a) : "l"(p));
    return a;
}
__device__ __forceinline__ void ldmatrix_x4(uint32_t* r, uint32_t addr) {
    asm volatile("ldmatrix.sync.aligned.m8n8.x4.shared.b16 {%0,%1,%2,%3}, [%4];"
                 : "=r"(r[0]), "=r"(r[1]), "=r"(r[2]), "=r"(r[3]) : "r"(addr));
}
__device__ __forceinline__ void mma16816(float* d, const uint32_t* a,
                                         uint32_t b0, uint32_t b1) {
    asm volatile(
        "mma.sync.aligned.m16n8k16.row.col.f32.f16.f16.f32 "
        "{%0,%1,%2,%3}, {%4,%5,%6,%7}, {%8,%9}, {%0,%1,%2,%3};"
        : "+f"(d[0]), "+f"(d[1]), "+f"(d[2]), "+f"(d[3])
        : "r"(a[0]), "r"(a[1]), "r"(a[2]), "r"(a[3]), "r"(b0), "r"(b1));
}
__device__ __forceinline__ void cpa16(uint32_t dst, const void* src) {
    asm volatile(
        "{ .reg .u64 g; cvta.to.global.u64 g, %1;"
        " cp.async.cg.shared.global [%0], [g], 16; }"
        :: "r"(dst), "l"(src) : "memory");
}
__device__ __forceinline__ void cpa16z(uint32_t dst, const void* src, bool p) {
    int sz = p ? 16 : 0;
    asm volatile(
        "{ .reg .u64 g; cvta.to.global.u64 g, %1;"
        " cp.async.cg.shared.global [%0], [g], 16, %2; }"
        :: "r"(dst), "l"(src), "r"(sz) : "memory");
}
__device__ __forceinline__ void cpa_commit() {
    asm volatile("cp.async.commit_group;" ::: "memory");
}
template <int N>
__device__ __forceinline__ void cpa_wait() {
    asm volatile("cp.async.wait_group %0;" :: "n"(N) : "memory");
}
__device__ __forceinline__ uint32_t pack2h(__half a, __half b) {
    uint16_t ua = *reinterpret_cast<uint16_t*>(&a);
    uint16_t ub = *reinterpret_cast<uint16_t*>(&b);
    return (uint32_t)ua | ((uint32_t)ub << 16);
}

// ---------------- pre-pass: W -> fp16 -----------------------------------------
__global__ __launch_bounds__(256)
void convert_w(const float* __restrict__ W) {
    int i = blockIdx.x * 256 + threadIdx.x;          // over float4s
    float4 v = reinterpret_cast<const float4*>(W)[i];
    __half h0 = __float2half_rn(v.x);
    __half h1 = __float2half_rn(v.y);
    __half h2 = __float2half_rn(v.z);
    __half h3 = __float2half_rn(v.w);
    reinterpret_cast<uint2*>(g_Wf)[i] = make_uint2(pack2h(h0, h1), pack2h(h2, h3));
}

// ---------------- pre-pass: x -> transposed fp16 hi/lo [b][l][c] --------------
__global__ __launch_bounds__(256)
void convert_x(const float* __restrict__ x) {
    __shared__ float t[32][33];
    const int tx = threadIdx.x, ty = threadIdx.y;
    const int lbase = blockIdx.x * 32;
    const int cbase = blockIdx.y * 32;
    const int b = blockIdx.z;
#pragma unroll
    for (int r = 0; r < 4; ++r) {
        int c = cbase + ty + r * 8;
        t[ty + r * 8][tx] = x[((size_t)b * CIN + c) * LLEN + lbase + tx];
    }
    __syncthreads();
#pragma unroll
    for (int r = 0; r < 4; ++r) {
        int l = lbase + ty + r * 8;
        float v = t[tx][ty + r * 8];
        __half h  = __float2half_rn(v);
        __half lo = __float2half_rn(v - __half2float(h));
        size_t o = ((size_t)b * LLEN + l) * CIN + cbase + tx;
        g_xh[o] = h;
        g_xl[o] = lo;
    }
}

// ---------------- main GEMM ---------------------------------------------------
__global__ __launch_bounds__(256, 2)
void fold_convT_mma(const float* __restrict__ bias, float* __restrict__ out)
{
    extern __shared__ char smem[];
    const uint32_t sbase = smem_u32(smem);

    const int tid  = threadIdx.x;
    const int lane = tid & 31;
    const int wid  = tid >> 5;
    const int wm   = wid >> 2;
    const int wn   = wid & 3;
    const int bb   = blockIdx.z;
    const int co0  = blockIdx.y * TM;
    const int l0   = blockIdx.x * TN;

    float acc[4][4][4];
#pragma unroll
    for (int i = 0; i < 4; ++i)
#pragma unroll
        for (int j = 0; j < 4; ++j)
#pragma unroll
            for (int q = 0; q < 4; ++q) acc[i][j][q] = 0.0f;

    const int a_elt  = (wm * 64 + (lane & 15)) * PS + (lane >> 4) * 8;
    const int b_lane = ((lane & 7) + ((lane >> 4) << 3)) * PS + ((lane >> 3) & 1) * 8;

    // W loader: each thread one 16-elem half-row (2 x 16B)
    const int arow  = tid >> 1;
    const int ahalf = (tid & 1) * 16;

    auto issue_W = [&](int it, int stage) {
        const int ci  = it >> 3;
        const int tap = it & 7;
        const size_t o = ((size_t)(tap * COUT + co0 + arow)) * CIN
                         + ci * KC + ahalf;
        const uint32_t d = sbase + stage * SA_ST + (arow * PS + ahalf) * 2;
        cpa16(d,      g_Wf + o);
        cpa16(d + 16, g_Wf + o + 8);
    };
    auto issue_strip = [&](int ci, int stage) {
        const int c0 = ci * KC;
        const uint32_t bh = sbase + SB_BASE + stage * SB_ST;
#pragma unroll
        for (int e = tid; e < SR * 4; e += 256) {
            int s = e >> 2;
            int q = (e & 3) * 8;
            int l = l0 + s - 7;
            bool p = (l >= 0) && (l < LLEN);
            int lc = p ? l : 0;
            size_t o = ((size_t)bb * LLEN + lc) * CIN + c0 + q;
            uint32_t d = bh + (s * PS + q) * 2;
            cpa16z(d,         g_xh + o, p);
            cpa16z(d + SB_HL, g_xl + o, p);
        }
    };

    // ---- prologue ----
    issue_strip(0, 0);
    issue_W(0, 0);
    cpa_commit();

#pragma unroll 1
    for (int it = 0; it < NIT; ++it) {
        const int ci  = it >> 3;
        const int tap = it & 7;

        cpa_wait<0>();
        __syncthreads();

        if (it < NIT - 1) {
            issue_W(it + 1, (it + 1) & 1);
            if (tap == 7) issue_strip(ci + 1, (ci + 1) & 1);
            cpa_commit();
        }

        const uint32_t sA_u  = sbase + (it & 1) * SA_ST;
        const uint32_t sBh_u = sbase + SB_BASE + (ci & 1) * SB_ST;
        const uint32_t sBl_u = sBh_u + SB_HL;
        const int rowOff = (wn * 32 + 7 - tap) * PS;

#pragma unroll
        for (int ks = 0; ks < 2; ++ks) {
            uint32_t Bh[8], Bl[8];
#pragma unroll
            for (int nfp = 0; nfp < 2; ++nfp) {
                uint32_t eb = (uint32_t)(b_lane + rowOff + nfp * 16 * PS
                                         + ks * 16) * 2;
                ldmatrix_x4(&Bh[nfp * 4], sBh_u + eb);
                ldmatrix_x4(&Bl[nfp * 4], sBl_u + eb);
            }

            uint32_t a[4][4];
            const uint32_t abyte = (uint32_t)(a_elt + ks * 16) * 2;
#pragma unroll
            for (int mf = 0; mf < 4; ++mf)
                ldmatrix_x4(a[mf], sA_u + abyte + mf * (16 * PS * 2));

            // W * Xh
#pragma unroll
            for (int mf = 0; mf < 4; ++mf)
#pragma unroll
                for (int nf = 0; nf < 4; ++nf)
                    mma16816(acc[mf][nf], a[mf], Bh[nf * 2], Bh[nf * 2 + 1]);
            // W * Xl
#pragma unroll
            for (int mf = 0; mf < 4; ++mf)
#pragma unroll
                for (int nf = 0; nf < 4; ++nf)
                    mma16816(acc[mf][nf], a[mf], Bl[nf * 2], Bl[nf * 2 + 1]);
        }
    }

    // ---- epilogue: add bias, store float2 per (row, 8-col frag) ----
    const int r  = lane >> 2;
    const int cq = (lane & 3) * 2;
#pragma unroll
    for (int mf = 0; mf < 4; ++mf) {
#pragma unroll
        for (int h2 = 0; h2 < 2; ++h2) {
            int row = co0 + wm * 64 + mf * 16 + h2 * 8 + r;
            float bv = __ldg(bias + row);
            float* orow = out + ((size_t)bb * COUT + row) * LLEN + l0 + wn * 32 + cq;
#pragma unroll
            for (int nf = 0; nf < 4; ++nf) {
                float2 v;
                v.x = acc[mf][nf][h2 * 2 + 0] + bv;
                v.y = acc[mf][nf][h2 * 2 + 1] + bv;
                *reinterpret_cast<float2*>(orow + nf * 8) = v;
            }
        }
    }
}

extern "C" void kernel_launch(void* const* d_in, const int* in_sizes, int n_in,
                              void* d_out, int out_size) {
    const float* x    = (const float*)d_in[0];   // [8, 512, 2048]
    const float* W    = (const float*)d_in[1];   // [4096, 512]
    const float* bias = (const float*)d_in[2];   // [512]
    float* out        = (float*)d_out;           // [8, 512, 2048]

    convert_w<<<(KW * COUT * CIN / 4) / 256, 256>>>(W);
    {
        dim3 g(LLEN / 32, CIN / 32, BATCH);
        dim3 b(32, 8);
        convert_x<<<g, b>>>(x);
    }

    cudaFuncSetAttribute(fold_convT_mma,
                         cudaFuncAttributeMaxDynamicSharedMemorySize, SMEM_TOTAL);
    dim3 grid(LLEN / TN, COUT / TM, BATCH);      // (16, 4, 8) = 512 CTAs
    fold_convT_mma<<<grid, 256, SMEM_TOTAL>>>(bias, out);
}

// round 11
// speedup vs baseline: 5.8534x; 1.4893x over previous
#include <cuda_runtime.h>
#include <cuda_fp16.h>
#include <cstdint>

// FoldTemporalConvTranspose1d via fp16 mma.sync HMMA GEMM (single-term).
//   y[b,co,l] = bias[co] + sum_{k=0..7} sum_c W[k*512+co,c] * x[b,c,l-k]
// R10: W and x both single RNE fp16 (fp32 accumulate). Measured W-only
// quantization error was 1.95e-4; adding x quantization -> ~2.8e-4 << 1e-3.
// MMA count is now 1x the math (was 2x). KC=64 halves barrier count.

#define CIN   512
#define COUT  512
#define LLEN  2048
#define BATCH 8
#define KW    8
#define TM    128
#define TN    128
#define KC    64
#define NCHUNK (CIN / KC)   // 8
#define NIT   (NCHUNK * KW) // 64
#define SR    136           // strip rows
#define PS    72            // padded smem row stride (fp16 units, 144 B)

// smem layout (bytes, dynamic)
#define SA_ST   18432                 // 128 * 72 * 2 (W tile per stage)
#define SB_BASE (2 * SA_ST)           // 36864
#define SB_ST   19584                 // 136 * 72 * 2 (x strip per stage)
#define SMEM_TOTAL (SB_BASE + 2 * SB_ST)  // 76032

// ---------------- scratch (static device globals; allocation-free) ----------
__device__ __align__(16) __half g_Wf[KW * COUT * CIN];           // 4 MB
__device__ __align__(16) __half g_xf[BATCH * LLEN * CIN];        // 16 MB [b][l][c]

// ---------------- helpers ----------------------------------------------------
__device__ __forceinline__ uint32_t smem_u32(const void* p) {
    uint32_t a;
    asm("{ .reg .u64 t; cvta.to.shared.u64 t, %1; cvt.u32.u64 %0, t; }"
        : "=r"(a) : "l"(p));
    return a;
}
__device__ __forceinline__ void ldmatrix_x4(uint32_t* r, uint32_t addr) {
    asm volatile("ldmatrix.sync.aligned.m8n8.x4.shared.b16 {%0,%1,%2,%3}, [%4];"
                 : "=r"(r[0]), "=r"(r[1]), "=r"(r[2]), "=r"(r[3]) : "r"(addr));
}
__device__ __forceinline__ void mma16816(float* d, const uint32_t* a,
                                         uint32_t b0, uint32_t b1) {
    asm volatile(
        "mma.sync.aligned.m16n8k16.row.col.f32.f16.f16.f32 "
        "{%0,%1,%2,%3}, {%4,%5,%6,%7}, {%8,%9}, {%0,%1,%2,%3};"
        : "+f"(d[0]), "+f"(d[1]), "+f"(d[2]), "+f"(d[3])
        : "r"(a[0]), "r"(a[1]), "r"(a[2]), "r"(a[3]), "r"(b0), "r"(b1));
}
__device__ __forceinline__ void cpa16(uint32_t dst, const void* src) {
    asm volatile(
        "{ .reg .u64 g; cvta.to.global.u64 g, %1;"
        " cp.async.cg.shared.global [%0], [g], 16; }"
        :: "r"(dst), "l"(src) : "memory");
}
__device__ __forceinline__ void cpa16z(uint32_t dst, const void* src, bool p) {
    int sz = p ? 16 : 0;
    asm volatile(
        "{ .reg .u64 g; cvta.to.global.u64 g, %1;"
        " cp.async.cg.shared.global [%0], [g], 16, %2; }"
        :: "r"(dst), "l"(src), "r"(sz) : "memory");
}
__device__ __forceinline__ void cpa_commit() {
    asm volatile("cp.async.commit_group;" ::: "memory");
}
template <int N>
__device__ __forceinline__ void cpa_wait() {
    asm volatile("cp.async.wait_group %0;" :: "n"(N) : "memory");
}
__device__ __forceinline__ uint32_t pack2h(__half a, __half b) {
    uint16_t ua = *reinterpret_cast<uint16_t*>(&a);
    uint16_t ub = *reinterpret_cast<uint16_t*>(&b);
    return (uint32_t)ua | ((uint32_t)ub << 16);
}

// ---------------- pre-pass: W -> fp16 -----------------------------------------
__global__ __launch_bounds__(256)
void convert_w(const float* __restrict__ W) {
    int i = blockIdx.x * 256 + threadIdx.x;          // over float4s
    float4 v = reinterpret_cast<const float4*>(W)[i];
    __half h0 = __float2half_rn(v.x);
    __half h1 = __float2half_rn(v.y);
    __half h2 = __float2half_rn(v.z);
    __half h3 = __float2half_rn(v.w);
    reinterpret_cast<uint2*>(g_Wf)[i] = make_uint2(pack2h(h0, h1), pack2h(h2, h3));
}

// ---------------- pre-pass: x -> transposed fp16 [b][l][c] --------------------
__global__ __launch_bounds__(256)
void convert_x(const float* __restrict__ x) {
    __shared__ float t[32][33];
    const int tx = threadIdx.x, ty = threadIdx.y;
    const int lbase = blockIdx.x * 32;
    const int cbase = blockIdx.y * 32;
    const int b = blockIdx.z;
#pragma unroll
    for (int r = 0; r < 4; ++r) {
        int c = cbase + ty + r * 8;
        t[ty + r * 8][tx] = x[((size_t)b * CIN + c) * LLEN + lbase + tx];
    }
    __syncthreads();
#pragma unroll
    for (int r = 0; r < 4; ++r) {
        int l = lbase + ty + r * 8;
        float v = t[tx][ty + r * 8];
        g_xf[((size_t)b * LLEN + l) * CIN + cbase + tx] = __float2half_rn(v);
    }
}

// ---------------- main GEMM ---------------------------------------------------
__global__ __launch_bounds__(256, 2)
void fold_convT_mma(const float* __restrict__ bias, float* __restrict__ out)
{
    extern __shared__ char smem[];
    const uint32_t sbase = smem_u32(smem);

    const int tid  = threadIdx.x;
    const int lane = tid & 31;
    const int wid  = tid >> 5;
    const int wm   = wid >> 2;
    const int wn   = wid & 3;
    const int bb   = blockIdx.z;
    const int co0  = blockIdx.y * TM;
    const int l0   = blockIdx.x * TN;

    float acc[4][4][4];
#pragma unroll
    for (int i = 0; i < 4; ++i)
#pragma unroll
        for (int j = 0; j < 4; ++j)
#pragma unroll
            for (int q = 0; q < 4; ++q) acc[i][j][q] = 0.0f;

    const int a_elt  = (wm * 64 + (lane & 15)) * PS + (lane >> 4) * 8;
    const int b_lane = ((lane & 7) + ((lane >> 4) << 3)) * PS + ((lane >> 3) & 1) * 8;

    // W loader: 2 threads per row, each thread 32 elements (4 x 16B)
    const int arow  = tid >> 1;
    const int ahalf = (tid & 1) * 32;

    auto issue_W = [&](int it, int stage) {
        const int ci  = it >> 3;
        const int tap = it & 7;
        const size_t o = ((size_t)(tap * COUT + co0 + arow)) * CIN
                         + ci * KC + ahalf;
        const uint32_t d = sbase + stage * SA_ST + (arow * PS + ahalf) * 2;
#pragma unroll
        for (int q = 0; q < 4; ++q)
            cpa16(d + q * 16, g_Wf + o + q * 8);
    };
    auto issue_strip = [&](int ci, int stage) {
        const int c0 = ci * KC;
        const uint32_t bh = sbase + SB_BASE + stage * SB_ST;
#pragma unroll
        for (int e = tid; e < SR * 8; e += 256) {   // 136 rows x 8 slots of 8 elem
            int s = e >> 3;
            int q = (e & 7) * 8;
            int l = l0 + s - 7;
            bool p = (l >= 0) && (l < LLEN);
            int lc = p ? l : 0;
            size_t o = ((size_t)bb * LLEN + lc) * CIN + c0 + q;
            cpa16z(bh + (s * PS + q) * 2, g_xf + o, p);
        }
    };

    // ---- prologue ----
    issue_strip(0, 0);
    issue_W(0, 0);
    cpa_commit();

#pragma unroll 1
    for (int it = 0; it < NIT; ++it) {
        const int ci  = it >> 3;
        const int tap = it & 7;

        cpa_wait<0>();
        __syncthreads();

        if (it < NIT - 1) {
            issue_W(it + 1, (it + 1) & 1);
            if (tap == 7) issue_strip(ci + 1, (ci + 1) & 1);
            cpa_commit();
        }

        const uint32_t sA_u = sbase + (it & 1) * SA_ST;
        const uint32_t sB_u = sbase + SB_BASE + (ci & 1) * SB_ST;
        const int rowOff = (wn * 32 + 7 - tap) * PS;

#pragma unroll
        for (int ks = 0; ks < 4; ++ks) {
            uint32_t B[8];
#pragma unroll
            for (int nfp = 0; nfp < 2; ++nfp) {
                uint32_t eb = (uint32_t)(b_lane + rowOff + nfp * 16 * PS
                                         + ks * 16) * 2;
                ldmatrix_x4(&B[nfp * 4], sB_u + eb);
            }

            uint32_t a[4][4];
            const uint32_t abyte = (uint32_t)(a_elt + ks * 16) * 2;
#pragma unroll
            for (int mf = 0; mf < 4; ++mf)
                ldmatrix_x4(a[mf], sA_u + abyte + mf * (16 * PS * 2));

#pragma unroll
            for (int mf = 0; mf < 4; ++mf)
#pragma unroll
                for (int nf = 0; nf < 4; ++nf)
                    mma16816(acc[mf][nf], a[mf], B[nf * 2], B[nf * 2 + 1]);
        }
    }

    // ---- epilogue: add bias, store float2 per (row, 8-col frag) ----
    const int r  = lane >> 2;
    const int cq = (lane & 3) * 2;
#pragma unroll
    for (int mf = 0; mf < 4; ++mf) {
#pragma unroll
        for (int h2 = 0; h2 < 2; ++h2) {
            int row = co0 + wm * 64 + mf * 16 + h2 * 8 + r;
            float bv = __ldg(bias + row);
            float* orow = out + ((size_t)bb * COUT + row) * LLEN + l0 + wn * 32 + cq;
#pragma unroll
            for (int nf = 0; nf < 4; ++nf) {
                float2 v;
                v.x = acc[mf][nf][h2 * 2 + 0] + bv;
                v.y = acc[mf][nf][h2 * 2 + 1] + bv;
                *reinterpret_cast<float2*>(orow + nf * 8) = v;
            }
        }
    }
}

extern "C" void kernel_launch(void* const* d_in, const int* in_sizes, int n_in,
                              void* d_out, int out_size) {
    const float* x    = (const float*)d_in[0];   // [8, 512, 2048]
    const float* W    = (const float*)d_in[1];   // [4096, 512]
    const float* bias = (const float*)d_in[2];   // [512]
    float* out        = (float*)d_out;           // [8, 512, 2048]

    convert_w<<<(KW * COUT * CIN / 4) / 256, 256>>>(W);
    {
        dim3 g(LLEN / 32, CIN / 32, BATCH);
        dim3 b(32, 8);
        convert_x<<<g, b>>>(x);
    }

    cudaFuncSetAttribute(fold_convT_mma,
                         cudaFuncAttributeMaxDynamicSharedMemorySize, SMEM_TOTAL);
    dim3 grid(LLEN / TN, COUT / TM, BATCH);      // (16, 4, 8) = 512 CTAs
    fold_convT_mma<<<grid, 256, SMEM_TOTAL>>>(bias, out);
}

// round 12
// speedup vs baseline: 6.3186x; 1.0795x over previous
#include <cuda_runtime.h>
#include <cuda_fp16.h>
#include <cstdint>

// FoldTemporalConvTranspose1d via fp16 mma.sync HMMA GEMM.
//   y[b,co,l] = bias[co] + sum_{k=0..7} sum_c W[k*512+co,c] * x[b,c,l-k]
// R11: batch-paired CTAs (N=256 per CTA: l-128 x 2 batches) halve the
// per-SM W cp.async op count, which R10 analysis showed is the binding
// resource (LDGSTS accept rate). W/x single fp16 RNE, fp32 accumulate.

#define CIN   512
#define COUT  512
#define LLEN  2048
#define BATCH 8
#define KW    8
#define TM    128
#define TN    128           // per batch; CTA covers 2 batches
#define KC    64
#define NCHUNK (CIN / KC)   // 8
#define NIT   (NCHUNK * KW) // 64
#define SR    136           // strip rows
#define PS    72            // padded smem row stride (fp16 units, 144 B)

// smem layout (bytes, dynamic)
#define SA_ST   18432                 // 128 * 72 * 2 (W tile per stage)
#define SB_BASE (2 * SA_ST)           // 36864
#define SB_ONE  19584                 // one strip: 136 * 72 * 2
#define SB_STG  (2 * SB_ONE)          // both batches, one stage
#define SMEM_TOTAL (SB_BASE + 2 * SB_STG)  // 115200

// ---------------- scratch (static device globals; allocation-free) ----------
__device__ __align__(16) __half g_Wf[KW * COUT * CIN];           // 4 MB
__device__ __align__(16) __half g_xf[BATCH * LLEN * CIN];        // 16 MB [b][l][c]

// ---------------- helpers ----------------------------------------------------
__device__ __forceinline__ uint32_t smem_u32(const void* p) {
    uint32_t a;
    asm("{ .reg .u64 t; cvta.to.shared.u64 t, %1; cvt.u32.u64 %0, t; }"
        : "=r"(a) : "l"(p));
    return a;
}
__device__ __forceinline__ void ldmatrix_x4(uint32_t* r, uint32_t addr) {
    asm volatile("ldmatrix.sync.aligned.m8n8.x4.shared.b16 {%0,%1,%2,%3}, [%4];"
                 : "=r"(r[0]), "=r"(r[1]), "=r"(r[2]), "=r"(r[3]) : "r"(addr));
}
__device__ __forceinline__ void mma16816(float* d, const uint32_t* a,
                                         uint32_t b0, uint32_t b1) {
    asm volatile(
        "mma.sync.aligned.m16n8k16.row.col.f32.f16.f16.f32 "
        "{%0,%1,%2,%3}, {%4,%5,%6,%7}, {%8,%9}, {%0,%1,%2,%3};"
        : "+f"(d[0]), "+f"(d[1]), "+f"(d[2]), "+f"(d[3])
        : "r"(a[0]), "r"(a[1]), "r"(a[2]), "r"(a[3]), "r"(b0), "r"(b1));
}
__device__ __forceinline__ void cpa16(uint32_t dst, const void* src) {
    asm volatile(
        "{ .reg .u64 g; cvta.to.global.u64 g, %1;"
        " cp.async.cg.shared.global [%0], [g], 16; }"
        :: "r"(dst), "l"(src) : "memory");
}
__device__ __forceinline__ void cpa16z(uint32_t dst, const void* src, bool p) {
    int sz = p ? 16 : 0;
    asm volatile(
        "{ .reg .u64 g; cvta.to.global.u64 g, %1;"
        " cp.async.cg.shared.global [%0], [g], 16, %2; }"
        :: "r"(dst), "l"(src), "r"(sz) : "memory");
}
__device__ __forceinline__ void cpa_commit() {
    asm volatile("cp.async.commit_group;" ::: "memory");
}
template <int N>
__device__ __forceinline__ void cpa_wait() {
    asm volatile("cp.async.wait_group %0;" :: "n"(N) : "memory");
}
__device__ __forceinline__ uint32_t pack2h(__half a, __half b) {
    uint16_t ua = *reinterpret_cast<uint16_t*>(&a);
    uint16_t ub = *reinterpret_cast<uint16_t*>(&b);
    return (uint32_t)ua | ((uint32_t)ub << 16);
}

// ---------------- pre-pass: W -> fp16 -----------------------------------------
__global__ __launch_bounds__(256)
void convert_w(const float* __restrict__ W) {
    int i = blockIdx.x * 256 + threadIdx.x;          // over float4s
    float4 v = reinterpret_cast<const float4*>(W)[i];
    __half h0 = __float2half_rn(v.x);
    __half h1 = __float2half_rn(v.y);
    __half h2 = __float2half_rn(v.z);
    __half h3 = __float2half_rn(v.w);
    reinterpret_cast<uint2*>(g_Wf)[i] = make_uint2(pack2h(h0, h1), pack2h(h2, h3));
}

// ---------------- pre-pass: x -> transposed fp16 [b][l][c] --------------------
__global__ __launch_bounds__(256)
void convert_x(const float* __restrict__ x) {
    __shared__ float t[32][33];
    const int tx = threadIdx.x, ty = threadIdx.y;
    const int lbase = blockIdx.x * 32;
    const int cbase = blockIdx.y * 32;
    const int b = blockIdx.z;
#pragma unroll
    for (int r = 0; r < 4; ++r) {
        int c = cbase + ty + r * 8;
        t[ty + r * 8][tx] = x[((size_t)b * CIN + c) * LLEN + lbase + tx];
    }
    __syncthreads();
#pragma unroll
    for (int r = 0; r < 4; ++r) {
        int l = lbase + ty + r * 8;
        float v = t[tx][ty + r * 8];
        g_xf[((size_t)b * LLEN + l) * CIN + cbase + tx] = __float2half_rn(v);
    }
}

// ---------------- main GEMM ---------------------------------------------------
__global__ __launch_bounds__(256, 1)
void fold_convT_mma(const float* __restrict__ bias, float* __restrict__ out)
{
    extern __shared__ char smem[];
    const uint32_t sbase = smem_u32(smem);

    const int tid  = threadIdx.x;
    const int lane = tid & 31;
    const int wid  = tid >> 5;
    const int wm   = wid >> 2;
    const int wn   = wid & 3;
    const int bb2  = blockIdx.z * 2;      // first batch of the pair
    const int co0  = blockIdx.y * TM;
    const int l0   = blockIdx.x * TN;

    float acc[4][8][4];                    // nf 0-3: batch0, nf 4-7: batch1
#pragma unroll
    for (int i = 0; i < 4; ++i)
#pragma unroll
        for (int j = 0; j < 8; ++j)
#pragma unroll
            for (int q = 0; q < 4; ++q) acc[i][j][q] = 0.0f;

    const int a_elt  = (wm * 64 + (lane & 15)) * PS + (lane >> 4) * 8;
    const int b_lane = ((lane & 7) + ((lane >> 4) << 3)) * PS + ((lane >> 3) & 1) * 8;

    // W loader: 2 threads per row, each thread 32 elements (4 x 16B)
    const int arow  = tid >> 1;
    const int ahalf = (tid & 1) * 32;

    auto issue_W = [&](int it, int stage) {
        const int ci  = it >> 3;
        const int tap = it & 7;
        const size_t o = ((size_t)(tap * COUT + co0 + arow)) * CIN
                         + ci * KC + ahalf;
        const uint32_t d = sbase + stage * SA_ST + (arow * PS + ahalf) * 2;
#pragma unroll
        for (int q = 0; q < 4; ++q)
            cpa16(d + q * 16, g_Wf + o + q * 8);
    };
    auto issue_strip = [&](int ci, int stage) {
        const int c0 = ci * KC;
#pragma unroll
        for (int bt = 0; bt < 2; ++bt) {
            const uint32_t bh = sbase + SB_BASE + stage * SB_STG + bt * SB_ONE;
            const size_t xb = (size_t)(bb2 + bt) * LLEN;
#pragma unroll
            for (int e = tid; e < SR * 8; e += 256) {
                int s = e >> 3;
                int q = (e & 7) * 8;
                int l = l0 + s - 7;
                bool p = (l >= 0) && (l < LLEN);
                int lc = p ? l : 0;
                size_t o = (xb + lc) * CIN + c0 + q;
                cpa16z(bh + (s * PS + q) * 2, g_xf + o, p);
            }
        }
    };

    // ---- prologue ----
    issue_strip(0, 0);
    issue_W(0, 0);
    cpa_commit();

#pragma unroll 1
    for (int it = 0; it < NIT; ++it) {
        const int ci  = it >> 3;
        const int tap = it & 7;

        cpa_wait<0>();
        __syncthreads();

        if (it < NIT - 1) {
            issue_W(it + 1, (it + 1) & 1);
            if (tap == 7) issue_strip(ci + 1, (ci + 1) & 1);
            cpa_commit();
        }

        const uint32_t sA_u  = sbase + (it & 1) * SA_ST;
        const uint32_t sB0_u = sbase + SB_BASE + (ci & 1) * SB_STG;
        const uint32_t sB1_u = sB0_u + SB_ONE;
        const int rowOff = (wn * 32 + 7 - tap) * PS;

#pragma unroll
        for (int ks = 0; ks < 4; ++ks) {
            uint32_t B[16];
#pragma unroll
            for (int nfp = 0; nfp < 2; ++nfp) {
                uint32_t eb = (uint32_t)(b_lane + rowOff + nfp * 16 * PS
                                         + ks * 16) * 2;
                ldmatrix_x4(&B[nfp * 4],     sB0_u + eb);
                ldmatrix_x4(&B[8 + nfp * 4], sB1_u + eb);
            }

            uint32_t a[4][4];
            const uint32_t abyte = (uint32_t)(a_elt + ks * 16) * 2;
#pragma unroll
            for (int mf = 0; mf < 4; ++mf)
                ldmatrix_x4(a[mf], sA_u + abyte + mf * (16 * PS * 2));

#pragma unroll
            for (int mf = 0; mf < 4; ++mf)
#pragma unroll
                for (int nf = 0; nf < 8; ++nf)
                    mma16816(acc[mf][nf], a[mf], B[nf * 2], B[nf * 2 + 1]);
        }
    }

    // ---- epilogue: add bias, store float2 per (row, 8-col frag) ----
    const int r  = lane >> 2;
    const int cq = (lane & 3) * 2;
#pragma unroll
    for (int bt = 0; bt < 2; ++bt) {
#pragma unroll
        for (int mf = 0; mf < 4; ++mf) {
#pragma unroll
            for (int h2 = 0; h2 < 2; ++h2) {
                int row = co0 + wm * 64 + mf * 16 + h2 * 8 + r;
                float bv = __ldg(bias + row);
                float* orow = out + ((size_t)(bb2 + bt) * COUT + row) * LLEN
                              + l0 + wn * 32 + cq;
#pragma unroll
                for (int nf = 0; nf < 4; ++nf) {
                    float2 v;
                    v.x = acc[mf][bt * 4 + nf][h2 * 2 + 0] + bv;
                    v.y = acc[mf][bt * 4 + nf][h2 * 2 + 1] + bv;
                    *reinterpret_cast<float2*>(orow + nf * 8) = v;
                }
            }
        }
    }
}

extern "C" void kernel_launch(void* const* d_in, const int* in_sizes, int n_in,
                              void* d_out, int out_size) {
    const float* x    = (const float*)d_in[0];   // [8, 512, 2048]
    const float* W    = (const float*)d_in[1];   // [4096, 512]
    const float* bias = (const float*)d_in[2];   // [512]
    float* out        = (float*)d_out;           // [8, 512, 2048]

    convert_w<<<(KW * COUT * CIN / 4) / 256, 256>>>(W);
    {
        dim3 g(LLEN / 32, CIN / 32, BATCH);
        dim3 b(32, 8);
        convert_x<<<g, b>>>(x);
    }

    cudaFuncSetAttribute(fold_convT_mma,
                         cudaFuncAttributeMaxDynamicSharedMemorySize, SMEM_TOTAL);
    dim3 grid(LLEN / TN, COUT / TM, BATCH / 2);  // (16, 4, 4) = 256 CTAs
    fold_convT_mma<<<grid, 256, SMEM_TOTAL>>>(bias, out);
}

// round 13
// speedup vs baseline: 7.3098x; 1.1569x over previous
#include <cuda_runtime.h>
#include <cuda_fp16.h>
#include <cstdint>

// FoldTemporalConvTranspose1d via fp16 mma.sync HMMA GEMM.
//   y[b,co,l] = bias[co] + sum_{k=0..7} sum_c W[k*512+co,c] * x[b,c,l-k]
// R12: W tiles pre-packed contiguous + pre-swizzled in global; main loop
// fetches each 16KB W tile with ONE cp.async.bulk (TMA path, mbarrier
// completion) instead of 1024 LDGSTS -> LSU issue pressure eliminated.

#define CIN   512
#define COUT  512
#define LLEN  2048
#define BATCH 8
#define KW    8
#define TM    128
#define TN    128           // per batch; CTA covers 2 batches
#define KC    64
#define NCHUNK (CIN / KC)   // 8
#define NIT   (NCHUNK * KW) // 64
#define SR    136           // strip rows
#define PS    72            // strip smem row stride (fp16 units, 144 B)

#define TILE_ELE   (128 * 64)        // one W tile (co x c), fp16
#define TILE_BYTES (TILE_ELE * 2)    // 16384

// smem layout (bytes, dynamic)
#define SM_MBAR 0                    // 2 mbarriers (16 B)
#define SW_BASE 1024                 // W stages: 2 x 16384
#define SB_BASE (SW_BASE + 2 * TILE_BYTES)   // 33792
#define SB_ONE  19584                // one strip: 136 * 72 * 2
#define SB_STG  (2 * SB_ONE)         // both batches, one stage
#define SMEM_TOTAL (SB_BASE + 2 * SB_STG)    // 112128

// ---------------- scratch (static device globals; allocation-free) ----------
// W tiled: [ci(8)][tap(8)][cy(4)] tiles of [row 128][col 64], col pre-swizzled
__device__ __align__(16) __half g_Wt[NCHUNK * KW * 4 * TILE_ELE];   // 4 MB
__device__ __align__(16) __half g_xf[BATCH * LLEN * CIN];           // 16 MB [b][l][c]

// ---------------- helpers ----------------------------------------------------
__device__ __forceinline__ uint32_t smem_u32(const void* p) {
    uint32_t a;
    asm("{ .reg .u64 t; cvta.to.shared.u64 t, %1; cvt.u32.u64 %0, t; }"
        : "=r"(a) : "l"(p));
    return a;
}
__device__ __forceinline__ void ldmatrix_x4(uint32_t* r, uint32_t addr) {
    asm volatile("ldmatrix.sync.aligned.m8n8.x4.shared.b16 {%0,%1,%2,%3}, [%4];"
                 : "=r"(r[0]), "=r"(r[1]), "=r"(r[2]), "=r"(r[3]) : "r"(addr));
}
__device__ __forceinline__ void mma16816(float* d, const uint32_t* a,
                                         uint32_t b0, uint32_t b1) {
    asm volatile(
        "mma.sync.aligned.m16n8k16.row.col.f32.f16.f16.f32 "
        "{%0,%1,%2,%3}, {%4,%5,%6,%7}, {%8,%9}, {%0,%1,%2,%3};"
        : "+f"(d[0]), "+f"(d[1]), "+f"(d[2]), "+f"(d[3])
        : "r"(a[0]), "r"(a[1]), "r"(a[2]), "r"(a[3]), "r"(b0), "r"(b1));
}
__device__ __forceinline__ void cpa16z(uint32_t dst, const void* src, bool p) {
    int sz = p ? 16 : 0;
    asm volatile(
        "{ .reg .u64 g; cvta.to.global.u64 g, %1;"
        " cp.async.cg.shared.global [%0], [g], 16, %2; }"
        :: "r"(dst), "l"(src), "r"(sz) : "memory");
}
__device__ __forceinline__ void cpa_commit() {
    asm volatile("cp.async.commit_group;" ::: "memory");
}
template <int N>
__device__ __forceinline__ void cpa_wait() {
    asm volatile("cp.async.wait_group %0;" :: "n"(N) : "memory");
}
// one-shot bulk copy global->shared, completion via mbarrier complete_tx
__device__ __forceinline__ void bulk_ld(uint32_t dst, const void* src,
                                        uint32_t bytes, uint32_t mbar) {
    asm volatile(
        "{ .reg .u64 g; cvta.to.global.u64 g, %1;"
        " cp.async.bulk.shared::cluster.global.mbarrier::complete_tx::bytes"
        " [%0], [g], %2, [%3]; }"
        :: "r"(dst), "l"(src), "r"(bytes), "r"(mbar) : "memory");
}
#define MBAR_INIT(a, c) \
    asm volatile("mbarrier.init.shared.b64 [%0], %1;" :: "r"(a), "r"(c) : "memory")
#define MBAR_EXPECT_TX(a, n) \
    asm volatile("mbarrier.arrive.expect_tx.shared.b64 _, [%0], %1;" \
                 :: "r"(a), "r"(n) : "memory")
#define MBAR_WAIT(a, ph) do {                                                     \
    uint32_t _m = (a), _p = (ph), _d;                                             \
    asm volatile("{ .reg .pred p;"                                                \
        "mbarrier.try_wait.parity.acquire.cta.shared::cta.b64 p, [%1], %2;"       \
        "selp.b32 %0,1,0,p; }" : "=r"(_d) : "r"(_m), "r"(_p) : "memory");         \
    if (!_d) {                                                                    \
        asm volatile("{ .reg .pred P1; WL_%=:"                                    \
            "mbarrier.try_wait.parity.acquire.cta.shared::cta.b64 P1, [%0], %1, 0x989680;" \
            "@P1 bra.uni WD_%=; bra.uni WL_%=; WD_%=: }"                          \
            :: "r"(_m), "r"(_p) : "memory");                                      \
    }                                                                             \
} while (0)

__device__ __forceinline__ uint32_t pack2h(__half a, __half b) {
    uint16_t ua = *reinterpret_cast<uint16_t*>(&a);
    uint16_t ub = *reinterpret_cast<uint16_t*>(&b);
    return (uint32_t)ua | ((uint32_t)ub << 16);
}

// ---------------- pre-pass: W -> fp16, tiled + swizzled -----------------------
// tile = (ci*8 + tap)*4 + cy ; inside: elem = r*64 + (c ^ ((r&7)<<3))
__global__ __launch_bounds__(256)
void convert_w_tiled(const float* __restrict__ W) {
    int idx = blockIdx.x * 256 + threadIdx.x;        // 16B chunks (8 fp16)
    int rowg = idx >> 6;                              // W row (tap*512+co)
    int c8   = (idx & 63) * 8;                        // c start
    const float* src = W + (size_t)rowg * CIN + c8;
    float4 v0 = reinterpret_cast<const float4*>(src)[0];
    float4 v1 = reinterpret_cast<const float4*>(src)[1];
    uint4 o;
    o.x = pack2h(__float2half_rn(v0.x), __float2half_rn(v0.y));
    o.y = pack2h(__float2half_rn(v0.z), __float2half_rn(v0.w));
    o.z = pack2h(__float2half_rn(v1.x), __float2half_rn(v1.y));
    o.w = pack2h(__float2half_rn(v1.z), __float2half_rn(v1.w));

    int tap = rowg >> 9;
    int co  = rowg & 511;
    int cy  = co >> 7;
    int r   = co & 127;
    int ci  = c8 >> 6;
    int cc  = c8 & 63;
    size_t dst = (size_t)(((ci * KW + tap) * 4 + cy)) * TILE_ELE
                 + r * 64 + (cc ^ ((r & 7) << 3));
    *reinterpret_cast<uint4*>(g_Wt + dst) = o;
}

// ---------------- pre-pass: x -> transposed fp16 [b][l][c] --------------------
__global__ __launch_bounds__(256)
void convert_x(const float* __restrict__ x) {
    __shared__ float t[32][33];
    const int tx = threadIdx.x, ty = threadIdx.y;
    const int lbase = blockIdx.x * 32;
    const int cbase = blockIdx.y * 32;
    const int b = blockIdx.z;
#pragma unroll
    for (int r = 0; r < 4; ++r) {
        int c = cbase + ty + r * 8;
        t[ty + r * 8][tx] = x[((size_t)b * CIN + c) * LLEN + lbase + tx];
    }
    __syncthreads();
#pragma unroll
    for (int r = 0; r < 4; ++r) {
        int l = lbase + ty + r * 8;
        float v = t[tx][ty + r * 8];
        g_xf[((size_t)b * LLEN + l) * CIN + cbase + tx] = __float2half_rn(v);
    }
}

// ---------------- main GEMM ---------------------------------------------------
__global__ __launch_bounds__(256, 1)
void fold_convT_mma(const float* __restrict__ bias, float* __restrict__ out)
{
    extern __shared__ char smem[];
    const uint32_t sbase = smem_u32(smem);

    const int tid  = threadIdx.x;
    const int lane = tid & 31;
    const int wid  = tid >> 5;
    const int wm   = wid >> 2;
    const int wn   = wid & 3;
    const int bb2  = blockIdx.z * 2;      // first batch of the pair
    const int co0  = blockIdx.y * TM;
    const int cy   = blockIdx.y;          // co-tile index for g_Wt
    const int l0   = blockIdx.x * TN;

    float acc[4][8][4];                    // nf 0-3: batch0, nf 4-7: batch1
#pragma unroll
    for (int i = 0; i < 4; ++i)
#pragma unroll
        for (int j = 0; j < 8; ++j)
#pragma unroll
            for (int q = 0; q < 4; ++q) acc[i][j][q] = 0.0f;

    // A addressing inside swizzled tile (elements):
    //   row = wm*64 + mf*16 + (lane&15); col = (lane>>4)*8 + ks*16, ^ (row&7)<<3
    const int arow_l = wm * 64 + (lane & 15);
    const int a_sv   = (arow_l & 7) << 3;        // mf*16 keeps row&7 invariant
    const int a_colb = (lane >> 4) * 8;
    // B (strip) addressing: same as R11
    const int b_lane = ((lane & 7) + ((lane >> 4) << 3)) * PS + ((lane >> 3) & 1) * 8;

    const uint32_t mb0 = sbase + SM_MBAR;
    const uint32_t mb1 = mb0 + 8;

    if (tid == 0) { MBAR_INIT(mb0, 1); MBAR_INIT(mb1, 1); }
    __syncthreads();

    auto issue_Wbulk = [&](int it, int stage) {
        // tile order matches it = ci*8 + tap
        const __half* src = g_Wt + (size_t)(it * 4 + cy) * TILE_ELE;
        const uint32_t mb = stage ? mb1 : mb0;
        MBAR_EXPECT_TX(mb, TILE_BYTES);
        bulk_ld(sbase + SW_BASE + stage * TILE_BYTES, src, TILE_BYTES, mb);
    };
    auto issue_strip = [&](int ci, int stage) {
        const int c0 = ci * KC;
#pragma unroll
        for (int bt = 0; bt < 2; ++bt) {
            const uint32_t bh = sbase + SB_BASE + stage * SB_STG + bt * SB_ONE;
            const size_t xb = (size_t)(bb2 + bt) * LLEN;
#pragma unroll
            for (int e = tid; e < SR * 8; e += 256) {
                int s = e >> 3;
                int q = (e & 7) * 8;
                int l = l0 + s - 7;
                bool p = (l >= 0) && (l < LLEN);
                int lc = p ? l : 0;
                size_t o = (xb + lc) * CIN + c0 + q;
                cpa16z(bh + (s * PS + q) * 2, g_xf + o, p);
            }
        }
    };

    // ---- prologue ----
    issue_strip(0, 0);
    cpa_commit();
    if (tid == 0) issue_Wbulk(0, 0);

    uint32_t wph[2] = {0, 0};

#pragma unroll 1
    for (int it = 0; it < NIT; ++it) {
        const int ci  = it >> 3;
        const int tap = it & 7;
        const int st  = it & 1;

        cpa_wait<0>();        // strip(ci) present (own thread's groups)
        __syncthreads();      // all warps done compute(it-1); strips visible

        if (it < NIT - 1) {   // prefetch it+1 (stage last read at it-1: safe)
            if (tid == 0) issue_Wbulk(it + 1, st ^ 1);
            if (tap == 7) { issue_strip(ci + 1, (ci + 1) & 1); cpa_commit(); }
        }

        // wait W tile(it)
        MBAR_WAIT(st ? mb1 : mb0, wph[st]);
        wph[st] ^= 1;

        const uint32_t sA_u  = sbase + SW_BASE + st * TILE_BYTES;
        const uint32_t sB0_u = sbase + SB_BASE + (ci & 1) * SB_STG;
        const uint32_t sB1_u = sB0_u + SB_ONE;
        const int rowOff = (wn * 32 + 7 - tap) * PS;

#pragma unroll
        for (int ks = 0; ks < 4; ++ks) {
            uint32_t B[16];
#pragma unroll
            for (int nfp = 0; nfp < 2; ++nfp) {
                uint32_t eb = (uint32_t)(b_lane + rowOff + nfp * 16 * PS
                                         + ks * 16) * 2;
                ldmatrix_x4(&B[nfp * 4],     sB0_u + eb);
                ldmatrix_x4(&B[8 + nfp * 4], sB1_u + eb);
            }

            uint32_t a[4][4];
            const int colsw = (a_colb + ks * 16) ^ a_sv;   // swizzled col
#pragma unroll
            for (int mf = 0; mf < 4; ++mf) {
                uint32_t ab = (uint32_t)((arow_l + mf * 16) * 64 + colsw) * 2;
                ldmatrix_x4(a[mf], sA_u + ab);
            }

#pragma unroll
            for (int mf = 0; mf < 4; ++mf)
#pragma unroll
                for (int nf = 0; nf < 8; ++nf)
                    mma16816(acc[mf][nf], a[mf], B[nf * 2], B[nf * 2 + 1]);
        }
    }

    // ---- epilogue: add bias, store float2 per (row, 8-col frag) ----
    const int r  = lane >> 2;
    const int cq = (lane & 3) * 2;
#pragma unroll
    for (int bt = 0; bt < 2; ++bt) {
#pragma unroll
        for (int mf = 0; mf < 4; ++mf) {
#pragma unroll
            for (int h2 = 0; h2 < 2; ++h2) {
                int row = co0 + wm * 64 + mf * 16 + h2 * 8 + r;
                float bv = __ldg(bias + row);
                float* orow = out + ((size_t)(bb2 + bt) * COUT + row) * LLEN
                              + l0 + wn * 32 + cq;
#pragma unroll
                for (int nf = 0; nf < 4; ++nf) {
                    float2 v;
                    v.x = acc[mf][bt * 4 + nf][h2 * 2 + 0] + bv;
                    v.y = acc[mf][bt * 4 + nf][h2 * 2 + 1] + bv;
                    *reinterpret_cast<float2*>(orow + nf * 8) = v;
                }
            }
        }
    }
}

extern "C" void kernel_launch(void* const* d_in, const int* in_sizes, int n_in,
                              void* d_out, int out_size) {
    const float* x    = (const float*)d_in[0];   // [8, 512, 2048]
    const float* W    = (const float*)d_in[1];   // [4096, 512]
    const float* bias = (const float*)d_in[2];   // [512]
    float* out        = (float*)d_out;           // [8, 512, 2048]

    convert_w_tiled<<<(KW * COUT * CIN / 8) / 256, 256>>>(W);
    {
        dim3 g(LLEN / 32, CIN / 32, BATCH);
        dim3 b(32, 8);
        convert_x<<<g, b>>>(x);
    }

    cudaFuncSetAttribute(fold_convT_mma,
                         cudaFuncAttributeMaxDynamicSharedMemorySize, SMEM_TOTAL);
    dim3 grid(LLEN / TN, COUT / TM, BATCH / 2);  // (16, 4, 4) = 256 CTAs
    fold_convT_mma<<<grid, 256, SMEM_TOTAL>>>(bias, out);
}

// round 14
// speedup vs baseline: 7.3614x; 1.0070x over previous
#include <cuda_runtime.h>
#include <cuda_fp16.h>
#include <cstdint>

// FoldTemporalConvTranspose1d via fp16 mma.sync HMMA GEMM.
//   y[b,co,l] = bias[co] + sum_{k=0..7} sum_c W[k*512+co,c] * x[b,c,l-k]
// R13: 512 threads / 16 warps (4 warps per SMSP to fill HMMA latency
// bubbles) + 3-stage cp.async.bulk W pipeline (full-wait never blocks).

#define CIN   512
#define COUT  512
#define LLEN  2048
#define BATCH 8
#define KW    8
#define TM    128
#define TN    128           // per batch; CTA covers 2 batches
#define KC    64
#define NCHUNK (CIN / KC)   // 8
#define NIT   (NCHUNK * KW) // 64
#define SR    136           // strip rows
#define PS    72            // strip smem row stride (fp16 units, 144 B)
#define NTHREADS 512

#define TILE_ELE   (128 * 64)        // one W tile (co x c), fp16
#define TILE_BYTES (TILE_ELE * 2)    // 16384
#define NSTAGE_W   3

// smem layout (bytes, dynamic)
#define SM_MBAR 0                    // 3 mbarriers (24 B)
#define SW_BASE 1024                 // W stages: 3 x 16384
#define SB_BASE (SW_BASE + NSTAGE_W * TILE_BYTES)   // 50176
#define SB_ONE  19584                // one strip: 136 * 72 * 2
#define SB_STG  (2 * SB_ONE)         // both batches, one stage
#define SMEM_TOTAL (SB_BASE + 2 * SB_STG)           // 128512

// ---------------- scratch (static device globals; allocation-free) ----------
// W tiled: [ci(8)][tap(8)][cy(4)] tiles of [row 128][col 64], col pre-swizzled
__device__ __align__(16) __half g_Wt[NCHUNK * KW * 4 * TILE_ELE];   // 4 MB
__device__ __align__(16) __half g_xf[BATCH * LLEN * CIN];           // 16 MB [b][l][c]

// ---------------- helpers ----------------------------------------------------
__device__ __forceinline__ uint32_t smem_u32(const void* p) {
    uint32_t a;
    asm("{ .reg .u64 t; cvta.to.shared.u64 t, %1; cvt.u32.u64 %0, t; }"
        : "=r"(a) : "l"(p));
    return a;
}
__device__ __forceinline__ void ldmatrix_x4(uint32_t* r, uint32_t addr) {
    asm volatile("ldmatrix.sync.aligned.m8n8.x4.shared.b16 {%0,%1,%2,%3}, [%4];"
                 : "=r"(r[0]), "=r"(r[1]), "=r"(r[2]), "=r"(r[3]) : "r"(addr));
}
__device__ __forceinline__ void mma16816(float* d, const uint32_t* a,
                                         uint32_t b0, uint32_t b1) {
    asm volatile(
        "mma.sync.aligned.m16n8k16.row.col.f32.f16.f16.f32 "
        "{%0,%1,%2,%3}, {%4,%5,%6,%7}, {%8,%9}, {%0,%1,%2,%3};"
        : "+f"(d[0]), "+f"(d[1]), "+f"(d[2]), "+f"(d[3])
        : "r"(a[0]), "r"(a[1]), "r"(a[2]), "r"(a[3]), "r"(b0), "r"(b1));
}
__device__ __forceinline__ void cpa16z(uint32_t dst, const void* src, bool p) {
    int sz = p ? 16 : 0;
    asm volatile(
        "{ .reg .u64 g; cvta.to.global.u64 g, %1;"
        " cp.async.cg.shared.global [%0], [g], 16, %2; }"
        :: "r"(dst), "l"(src), "r"(sz) : "memory");
}
__device__ __forceinline__ void cpa_commit() {
    asm volatile("cp.async.commit_group;" ::: "memory");
}
template <int N>
__device__ __forceinline__ void cpa_wait() {
    asm volatile("cp.async.wait_group %0;" :: "n"(N) : "memory");
}
__device__ __forceinline__ void bulk_ld(uint32_t dst, const void* src,
                                        uint32_t bytes, uint32_t mbar) {
    asm volatile(
        "{ .reg .u64 g; cvta.to.global.u64 g, %1;"
        " cp.async.bulk.shared::cluster.global.mbarrier::complete_tx::bytes"
        " [%0], [g], %2, [%3]; }"
        :: "r"(dst), "l"(src), "r"(bytes), "r"(mbar) : "memory");
}
#define MBAR_INIT(a, c) \
    asm volatile("mbarrier.init.shared.b64 [%0], %1;" :: "r"(a), "r"(c) : "memory")
#define MBAR_EXPECT_TX(a, n) \
    asm volatile("mbarrier.arrive.expect_tx.shared.b64 _, [%0], %1;" \
                 :: "r"(a), "r"(n) : "memory")
#define MBAR_WAIT(a, ph) do {                                                     \
    uint32_t _m = (a), _p = (ph), _d;                                             \
    asm volatile("{ .reg .pred p;"                                                \
        "mbarrier.try_wait.parity.acquire.cta.shared::cta.b64 p, [%1], %2;"       \
        "selp.b32 %0,1,0,p; }" : "=r"(_d) : "r"(_m), "r"(_p) : "memory");         \
    if (!_d) {                                                                    \
        asm volatile("{ .reg .pred P1; WL_%=:"                                    \
            "mbarrier.try_wait.parity.acquire.cta.shared::cta.b64 P1, [%0], %1, 0x989680;" \
            "@P1 bra.uni WD_%=; bra.uni WL_%=; WD_%=: }"                          \
            :: "r"(_m), "r"(_p) : "memory");                                      \
    }                                                                             \
} while (0)

__device__ __forceinline__ uint32_t pack2h(__half a, __half b) {
    uint16_t ua = *reinterpret_cast<uint16_t*>(&a);
    uint16_t ub = *reinterpret_cast<uint16_t*>(&b);
    return (uint32_t)ua | ((uint32_t)ub << 16);
}

// ---------------- pre-pass: W -> fp16, tiled + swizzled -----------------------
__global__ __launch_bounds__(256)
void convert_w_tiled(const float* __restrict__ W) {
    int idx = blockIdx.x * 256 + threadIdx.x;        // 16B chunks (8 fp16)
    int rowg = idx >> 6;                              // W row (tap*512+co)
    int c8   = (idx & 63) * 8;                        // c start
    const float* src = W + (size_t)rowg * CIN + c8;
    float4 v0 = reinterpret_cast<const float4*>(src)[0];
    float4 v1 = reinterpret_cast<const float4*>(src)[1];
    uint4 o;
    o.x = pack2h(__float2half_rn(v0.x), __float2half_rn(v0.y));
    o.y = pack2h(__float2half_rn(v0.z), __float2half_rn(v0.w));
    o.z = pack2h(__float2half_rn(v1.x), __float2half_rn(v1.y));
    o.w = pack2h(__float2half_rn(v1.z), __float2half_rn(v1.w));

    int tap = rowg >> 9;
    int co  = rowg & 511;
    int cy  = co >> 7;
    int r   = co & 127;
    int ci  = c8 >> 6;
    int cc  = c8 & 63;
    size_t dst = (size_t)(((ci * KW + tap) * 4 + cy)) * TILE_ELE
                 + r * 64 + (cc ^ ((r & 7) << 3));
    *reinterpret_cast<uint4*>(g_Wt + dst) = o;
}

// ---------------- pre-pass: x -> transposed fp16 [b][l][c] --------------------
__global__ __launch_bounds__(256)
void convert_x(const float* __restrict__ x) {
    __shared__ float t[32][33];
    const int tx = threadIdx.x, ty = threadIdx.y;
    const int lbase = blockIdx.x * 32;
    const int cbase = blockIdx.y * 32;
    const int b = blockIdx.z;
#pragma unroll
    for (int r = 0; r < 4; ++r) {
        int c = cbase + ty + r * 8;
        t[ty + r * 8][tx] = x[((size_t)b * CIN + c) * LLEN + lbase + tx];
    }
    __syncthreads();
#pragma unroll
    for (int r = 0; r < 4; ++r) {
        int l = lbase + ty + r * 8;
        float v = t[tx][ty + r * 8];
        g_xf[((size_t)b * LLEN + l) * CIN + cbase + tx] = __float2half_rn(v);
    }
}

// ---------------- main GEMM ---------------------------------------------------
__global__ __launch_bounds__(NTHREADS, 1)
void fold_convT_mma(const float* __restrict__ bias, float* __restrict__ out)
{
    extern __shared__ char smem[];
    const uint32_t sbase = smem_u32(smem);

    const int tid  = threadIdx.x;
    const int lane = tid & 31;
    const int wid  = tid >> 5;           // 0..15
    const int wm   = wid >> 3;           // 0..1 -> co 64-block
    const int wn   = wid & 7;            // 0..7
    const int bt   = wn >> 2;            // strip (batch) 0/1
    const int wnn  = wn & 3;             // l 32-block within strip
    const int bb2  = blockIdx.z * 2;
    const int co0  = blockIdx.y * TM;
    const int cy   = blockIdx.y;
    const int l0   = blockIdx.x * TN;

    float acc[4][4][4];                  // mf x nf(4 of n8) x regs
#pragma unroll
    for (int i = 0; i < 4; ++i)
#pragma unroll
        for (int j = 0; j < 4; ++j)
#pragma unroll
            for (int q = 0; q < 4; ++q) acc[i][j][q] = 0.0f;

    // A addressing inside swizzled W tile
    const int arow_l = wm * 64 + (lane & 15);
    const int a_sv   = (arow_l & 7) << 3;
    const int a_colb = (lane >> 4) * 8;
    // B (strip) ldmatrix lane offset
    const int b_lane = ((lane & 7) + ((lane >> 4) << 3)) * PS + ((lane >> 3) & 1) * 8;

    const uint32_t mb = sbase + SM_MBAR;     // 3 mbarriers, 8 B apart

    if (tid == 0) {
#pragma unroll
        for (int s = 0; s < NSTAGE_W; ++s) MBAR_INIT(mb + s * 8, 1);
    }
    __syncthreads();

    auto issue_Wbulk = [&](int it) {
        const int st = it % NSTAGE_W;
        const __half* src = g_Wt + (size_t)(it * 4 + cy) * TILE_ELE;
        MBAR_EXPECT_TX(mb + st * 8, TILE_BYTES);
        bulk_ld(sbase + SW_BASE + st * TILE_BYTES, src, TILE_BYTES, mb + st * 8);
    };
    auto issue_strip = [&](int ci, int stage) {
        const int c0 = ci * KC;
#pragma unroll
        for (int e = tid; e < SR * 8 * 2; e += NTHREADS) {
            int sb = (e >= SR * 8) ? 1 : 0;
            int in = e - sb * SR * 8;
            int s = in >> 3;
            int q = (in & 7) * 8;
            int l = l0 + s - 7;
            bool p = (l >= 0) && (l < LLEN);
            int lc = p ? l : 0;
            size_t o = ((size_t)(bb2 + sb) * LLEN + lc) * CIN + c0 + q;
            cpa16z(sbase + SB_BASE + stage * SB_STG + sb * SB_ONE
                   + (s * PS + q) * 2, g_xf + o, p);
        }
    };

    // ---- prologue: strip(0) + W(0), W(1) ----
    issue_strip(0, 0);
    cpa_commit();
    if (tid == 0) { issue_Wbulk(0); issue_Wbulk(1); }

    uint32_t wph[NSTAGE_W] = {0, 0, 0};

#pragma unroll 1
    for (int it = 0; it < NIT; ++it) {
        const int ci  = it >> 3;
        const int tap = it & 7;
        const int st  = it % NSTAGE_W;

        cpa_wait<0>();        // strip(ci) present (own thread's groups)
        __syncthreads();      // all warps done compute(it-1)

        if (it + 2 < NIT && tid == 0) issue_Wbulk(it + 2);
        if (tap == 7 && it < NIT - 1) { issue_strip(ci + 1, (ci + 1) & 1); cpa_commit(); }

        MBAR_WAIT(mb + st * 8, wph[st]);   // W tile(it); issued at it-2
        wph[st] ^= 1;

        const uint32_t sA_u = sbase + SW_BASE + st * TILE_BYTES;
        const uint32_t sB_u = sbase + SB_BASE + (ci & 1) * SB_STG + bt * SB_ONE;
        const int rowOff = (wnn * 32 + 7 - tap) * PS;

#pragma unroll
        for (int ks = 0; ks < 4; ++ks) {
            uint32_t B[8];
#pragma unroll
            for (int nfp = 0; nfp < 2; ++nfp) {
                uint32_t eb = (uint32_t)(b_lane + rowOff + nfp * 16 * PS
                                         + ks * 16) * 2;
                ldmatrix_x4(&B[nfp * 4], sB_u + eb);
            }

            uint32_t a[4][4];
            const int colsw = (a_colb + ks * 16) ^ a_sv;
#pragma unroll
            for (int mf = 0; mf < 4; ++mf) {
                uint32_t ab = (uint32_t)((arow_l + mf * 16) * 64 + colsw) * 2;
                ldmatrix_x4(a[mf], sA_u + ab);
            }

#pragma unroll
            for (int mf = 0; mf < 4; ++mf)
#pragma unroll
                for (int nf = 0; nf < 4; ++nf)
                    mma16816(acc[mf][nf], a[mf], B[nf * 2], B[nf * 2 + 1]);
        }
    }

    // ---- epilogue: add bias, store float2 per (row, 8-col frag) ----
    const int r  = lane >> 2;
    const int cq = (lane & 3) * 2;
#pragma unroll
    for (int mf = 0; mf < 4; ++mf) {
#pragma unroll
        for (int h2 = 0; h2 < 2; ++h2) {
            int row = co0 + wm * 64 + mf * 16 + h2 * 8 + r;
            float bv = __ldg(bias + row);
            float* orow = out + ((size_t)(bb2 + bt) * COUT + row) * LLEN
                          + l0 + wnn * 32 + cq;
#pragma unroll
            for (int nf = 0; nf < 4; ++nf) {
                float2 v;
                v.x = acc[mf][nf][h2 * 2 + 0] + bv;
                v.y = acc[mf][nf][h2 * 2 + 1] + bv;
                *reinterpret_cast<float2*>(orow + nf * 8) = v;
            }
        }
    }
}

extern "C" void kernel_launch(void* const* d_in, const int* in_sizes, int n_in,
                              void* d_out, int out_size) {
    const float* x    = (const float*)d_in[0];   // [8, 512, 2048]
    const float* W    = (const float*)d_in[1];   // [4096, 512]
    const float* bias = (const float*)d_in[2];   // [512]
    float* out        = (float*)d_out;           // [8, 512, 2048]

    convert_w_tiled<<<(KW * COUT * CIN / 8) / 256, 256>>>(W);
    {
        dim3 g(LLEN / 32, CIN / 32, BATCH);
        dim3 b(32, 8);
        convert_x<<<g, b>>>(x);
    }

    cudaFuncSetAttribute(fold_convT_mma,
                         cudaFuncAttributeMaxDynamicSharedMemorySize, SMEM_TOTAL);
    dim3 grid(LLEN / TN, COUT / TM, BATCH / 2);  // (16, 4, 4) = 256 CTAs
    fold_convT_mma<<<grid, NTHREADS, SMEM_TOTAL>>>(bias, out);
}

// round 15
// speedup vs baseline: 7.7674x; 1.0552x over previous
#include <cuda_runtime.h>
#include <cuda_fp16.h>
#include <cstdint>

// FoldTemporalConvTranspose1d via fp16 mma.sync HMMA GEMM.
//   y[b,co,l] = bias[co] + sum_{k=0..7} sum_c W[k*512+co,c] * x[b,c,l-k]
// R14: 6-stage W bulk pipeline + one __syncthreads per TWO taps,
// strip prefetch issued at tap 4 with lazy wait, fused convert pre-pass.

#define CIN   512
#define COUT  512
#define LLEN  2048
#define BATCH 8
#define KW    8
#define TM    128
#define TN    128           // per batch; CTA covers 2 batches
#define KC    64
#define NCHUNK (CIN / KC)   // 8
#define NIT   (NCHUNK * KW) // 64
#define SR    136           // strip rows
#define PS    72            // strip smem row stride (fp16 units, 144 B)
#define NTHREADS 512

#define TILE_ELE   (128 * 64)        // one W tile (co x c), fp16
#define TILE_BYTES (TILE_ELE * 2)    // 16384
#define NSTAGE_W   6

// smem layout (bytes, dynamic)
#define SM_MBAR 0                    // 6 mbarriers (48 B)
#define SW_BASE 1024                 // W stages: 6 x 16384 = 98304
#define SB_BASE (SW_BASE + NSTAGE_W * TILE_BYTES)   // 99328
#define SB_ONE  19584                // one strip: 136 * 72 * 2
#define SB_STG  (2 * SB_ONE)         // both batches, one stage
#define SMEM_TOTAL (SB_BASE + 2 * SB_STG)           // 177664

// ---------------- scratch (static device globals; allocation-free) ----------
__device__ __align__(16) __half g_Wt[NCHUNK * KW * 4 * TILE_ELE];   // 4 MB
__device__ __align__(16) __half g_xf[BATCH * LLEN * CIN];           // 16 MB [b][l][c]

// ---------------- helpers ----------------------------------------------------
__device__ __forceinline__ uint32_t smem_u32(const void* p) {
    uint32_t a;
    asm("{ .reg .u64 t; cvta.to.shared.u64 t, %1; cvt.u32.u64 %0, t; }"
        : "=r"(a) : "l"(p));
    return a;
}
__device__ __forceinline__ void ldmatrix_x4(uint32_t* r, uint32_t addr) {
    asm volatile("ldmatrix.sync.aligned.m8n8.x4.shared.b16 {%0,%1,%2,%3}, [%4];"
                 : "=r"(r[0]), "=r"(r[1]), "=r"(r[2]), "=r"(r[3]) : "r"(addr));
}
__device__ __forceinline__ void mma16816(float* d, const uint32_t* a,
                                         uint32_t b0, uint32_t b1) {
    asm volatile(
        "mma.sync.aligned.m16n8k16.row.col.f32.f16.f16.f32 "
        "{%0,%1,%2,%3}, {%4,%5,%6,%7}, {%8,%9}, {%0,%1,%2,%3};"
        : "+f"(d[0]), "+f"(d[1]), "+f"(d[2]), "+f"(d[3])
        : "r"(a[0]), "r"(a[1]), "r"(a[2]), "r"(a[3]), "r"(b0), "r"(b1));
}
__device__ __forceinline__ void cpa16z(uint32_t dst, const void* src, bool p) {
    int sz = p ? 16 : 0;
    asm volatile(
        "{ .reg .u64 g; cvta.to.global.u64 g, %1;"
        " cp.async.cg.shared.global [%0], [g], 16, %2; }"
        :: "r"(dst), "l"(src), "r"(sz) : "memory");
}
__device__ __forceinline__ void cpa_commit() {
    asm volatile("cp.async.commit_group;" ::: "memory");
}
template <int N>
__device__ __forceinline__ void cpa_wait() {
    asm volatile("cp.async.wait_group %0;" :: "n"(N) : "memory");
}
__device__ __forceinline__ void bulk_ld(uint32_t dst, const void* src,
                                        uint32_t bytes, uint32_t mbar) {
    asm volatile(
        "{ .reg .u64 g; cvta.to.global.u64 g, %1;"
        " cp.async.bulk.shared::cluster.global.mbarrier::complete_tx::bytes"
        " [%0], [g], %2, [%3]; }"
        :: "r"(dst), "l"(src), "r"(bytes), "r"(mbar) : "memory");
}
#define MBAR_INIT(a, c) \
    asm volatile("mbarrier.init.shared.b64 [%0], %1;" :: "r"(a), "r"(c) : "memory")
#define MBAR_EXPECT_TX(a, n) \
    asm volatile("mbarrier.arrive.expect_tx.shared.b64 _, [%0], %1;" \
                 :: "r"(a), "r"(n) : "memory")
#define MBAR_WAIT(a, ph) do {                                                     \
    uint32_t _m = (a), _p = (ph), _d;                                             \
    asm volatile("{ .reg .pred p;"                                                \
        "mbarrier.try_wait.parity.acquire.cta.shared::cta.b64 p, [%1], %2;"       \
        "selp.b32 %0,1,0,p; }" : "=r"(_d) : "r"(_m), "r"(_p) : "memory");         \
    if (!_d) {                                                                    \
        asm volatile("{ .reg .pred P1; WL_%=:"                                    \
            "mbarrier.try_wait.parity.acquire.cta.shared::cta.b64 P1, [%0], %1, 0x989680;" \
            "@P1 bra.uni WD_%=; bra.uni WL_%=; WD_%=: }"                          \
            :: "r"(_m), "r"(_p) : "memory");                                      \
    }                                                                             \
} while (0)

__device__ __forceinline__ uint32_t pack2h(__half a, __half b) {
    uint16_t ua = *reinterpret_cast<uint16_t*>(&a);
    uint16_t ub = *reinterpret_cast<uint16_t*>(&b);
    return (uint32_t)ua | ((uint32_t)ub << 16);
}

// ---------------- fused pre-pass: W tiling + x transpose ----------------------
// blocks [0, 1024): W -> fp16 tiled+swizzled; blocks [1024, 9216): x transpose
#define WBLOCKS 1024
__global__ __launch_bounds__(256)
void convert_fused(const float* __restrict__ W, const float* __restrict__ x) {
    if (blockIdx.x < WBLOCKS) {
        int idx = blockIdx.x * 256 + threadIdx.x;        // 16B chunks (8 fp16)
        int rowg = idx >> 6;                              // W row (tap*512+co)
        int c8   = (idx & 63) * 8;                        // c start
        const float* src = W + (size_t)rowg * CIN + c8;
        float4 v0 = reinterpret_cast<const float4*>(src)[0];
        float4 v1 = reinterpret_cast<const float4*>(src)[1];
        uint4 o;
        o.x = pack2h(__float2half_rn(v0.x), __float2half_rn(v0.y));
        o.y = pack2h(__float2half_rn(v0.z), __float2half_rn(v0.w));
        o.z = pack2h(__float2half_rn(v1.x), __float2half_rn(v1.y));
        o.w = pack2h(__float2half_rn(v1.z), __float2half_rn(v1.w));

        int tap = rowg >> 9;
        int co  = rowg & 511;
        int cy  = co >> 7;
        int r   = co & 127;
        int ci  = c8 >> 6;
        int cc  = c8 & 63;
        size_t dst = (size_t)(((ci * KW + tap) * 4 + cy)) * TILE_ELE
                     + r * 64 + (cc ^ ((r & 7) << 3));
        *reinterpret_cast<uint4*>(g_Wt + dst) = o;
    } else {
        __shared__ float t[32][33];
        int i = blockIdx.x - WBLOCKS;          // 0 .. 8191
        const int b  = i >> 10;                // / (64*16)
        const int rem = i & 1023;
        const int cbase = (rem >> 6) * 32;
        const int lbase = (rem & 63) * 32;
        const int tx = threadIdx.x & 31;
        const int ty = threadIdx.x >> 5;
#pragma unroll
        for (int r = 0; r < 4; ++r) {
            int c = cbase + ty + r * 8;
            t[ty + r * 8][tx] = x[((size_t)b * CIN + c) * LLEN + lbase + tx];
        }
        __syncthreads();
#pragma unroll
        for (int r = 0; r < 4; ++r) {
            int l = lbase + ty + r * 8;
            float v = t[tx][ty + r * 8];
            g_xf[((size_t)b * LLEN + l) * CIN + cbase + tx] = __float2half_rn(v);
        }
    }
}

// ---------------- main GEMM ---------------------------------------------------
__global__ __launch_bounds__(NTHREADS, 1)
void fold_convT_mma(const float* __restrict__ bias, float* __restrict__ out)
{
    extern __shared__ char smem[];
    const uint32_t sbase = smem_u32(smem);

    const int tid  = threadIdx.x;
    const int lane = tid & 31;
    const int wid  = tid >> 5;           // 0..15
    const int wm   = wid >> 3;           // 0..1 -> co 64-block
    const int wn   = wid & 7;            // 0..7
    const int bt   = wn >> 2;            // strip (batch) 0/1
    const int wnn  = wn & 3;             // l 32-block within strip
    const int bb2  = blockIdx.z * 2;
    const int co0  = blockIdx.y * TM;
    const int cy   = blockIdx.y;
    const int l0   = blockIdx.x * TN;

    float acc[4][4][4];
#pragma unroll
    for (int i = 0; i < 4; ++i)
#pragma unroll
        for (int j = 0; j < 4; ++j)
#pragma unroll
            for (int q = 0; q < 4; ++q) acc[i][j][q] = 0.0f;

    // A addressing inside swizzled W tile
    const int arow_l = wm * 64 + (lane & 15);
    const int a_sv   = (arow_l & 7) << 3;
    const int a_colb = (lane >> 4) * 8;
    // B (strip) ldmatrix lane offset
    const int b_lane = ((lane & 7) + ((lane >> 4) << 3)) * PS + ((lane >> 3) & 1) * 8;

    const uint32_t mb = sbase + SM_MBAR;     // 6 mbarriers, 8 B apart

    if (tid == 0) {
#pragma unroll
        for (int s = 0; s < NSTAGE_W; ++s) MBAR_INIT(mb + s * 8, 1);
    }
    __syncthreads();

    auto issue_Wbulk = [&](int it) {
        const int st = it % NSTAGE_W;
        const __half* src = g_Wt + (size_t)(it * 4 + cy) * TILE_ELE;
        MBAR_EXPECT_TX(mb + st * 8, TILE_BYTES);
        bulk_ld(sbase + SW_BASE + st * TILE_BYTES, src, TILE_BYTES, mb + st * 8);
    };
    auto issue_strip = [&](int ci, int stage) {
        const int c0 = ci * KC;
#pragma unroll
        for (int e = tid; e < SR * 8 * 2; e += NTHREADS) {
            int sb = (e >= SR * 8) ? 1 : 0;
            int in = e - sb * SR * 8;
            int s = in >> 3;
            int q = (in & 7) * 8;
            int l = l0 + s - 7;
            bool p = (l >= 0) && (l < LLEN);
            int lc = p ? l : 0;
            size_t o = ((size_t)(bb2 + sb) * LLEN + lc) * CIN + c0 + q;
            cpa16z(sbase + SB_BASE + stage * SB_STG + sb * SB_ONE
                   + (s * PS + q) * 2, g_xf + o, p);
        }
    };

    // ---- prologue: strip(0) + W(0..2) ----
    issue_strip(0, 0);
    cpa_commit();
    if (tid == 0) { issue_Wbulk(0); issue_Wbulk(1); issue_Wbulk(2); }

    uint32_t wph[NSTAGE_W] = {0, 0, 0, 0, 0, 0};

    // 32 groups of 2 taps; one __syncthreads per group
#pragma unroll 1
    for (int g = 0; g < NIT / 2; ++g) {
        const int it0 = g * 2;
        const int ci  = it0 >> 3;

        if ((g & 3) == 0) cpa_wait<0>();  // new chunk: strip(ci) must be in
        __syncthreads();                  // all warps done with group g-1

        if (tid == 0) {                   // keep 3 W tiles in flight
            if (it0 + 3 < NIT) issue_Wbulk(it0 + 3);
            if (it0 + 4 < NIT) issue_Wbulk(it0 + 4);
        }
        if ((g & 3) == 2 && ci + 1 < NCHUNK) {   // tap 4: prefetch next strip
            issue_strip(ci + 1, (ci + 1) & 1);
            cpa_commit();
        }

        const uint32_t sB_u = sbase + SB_BASE + (ci & 1) * SB_STG + bt * SB_ONE;

#pragma unroll
        for (int half = 0; half < 2; ++half) {
            const int it  = it0 + half;
            const int tap = it & 7;
            const int st  = it % NSTAGE_W;

            MBAR_WAIT(mb + st * 8, wph[st]);
            wph[st] ^= 1;

            const uint32_t sA_u = sbase + SW_BASE + st * TILE_BYTES;
            const int rowOff = (wnn * 32 + 7 - tap) * PS;

#pragma unroll
            for (int ks = 0; ks < 4; ++ks) {
                uint32_t B[8];
#pragma unroll
                for (int nfp = 0; nfp < 2; ++nfp) {
                    uint32_t eb = (uint32_t)(b_lane + rowOff + nfp * 16 * PS
                                             + ks * 16) * 2;
                    ldmatrix_x4(&B[nfp * 4], sB_u + eb);
                }

                uint32_t a[4][4];
                const int colsw = (a_colb + ks * 16) ^ a_sv;
#pragma unroll
                for (int mf = 0; mf < 4; ++mf) {
                    uint32_t ab = (uint32_t)((arow_l + mf * 16) * 64 + colsw) * 2;
                    ldmatrix_x4(a[mf], sA_u + ab);
                }

#pragma unroll
                for (int mf = 0; mf < 4; ++mf)
#pragma unroll
                    for (int nf = 0; nf < 4; ++nf)
                        mma16816(acc[mf][nf], a[mf], B[nf * 2], B[nf * 2 + 1]);
            }
        }
    }

    // ---- epilogue: add bias, store float2 per (row, 8-col frag) ----
    const int r  = lane >> 2;
    const int cq = (lane & 3) * 2;
#pragma unroll
    for (int mf = 0; mf < 4; ++mf) {
#pragma unroll
        for (int h2 = 0; h2 < 2; ++h2) {
            int row = co0 + wm * 64 + mf * 16 + h2 * 8 + r;
            float bv = __ldg(bias + row);
            float* orow = out + ((size_t)(bb2 + bt) * COUT + row) * LLEN
                          + l0 + wnn * 32 + cq;
#pragma unroll
            for (int nf = 0; nf < 4; ++nf) {
                float2 v;
                v.x = acc[mf][nf][h2 * 2 + 0] + bv;
                v.y = acc[mf][nf][h2 * 2 + 1] + bv;
                *reinterpret_cast<float2*>(orow + nf * 8) = v;
            }
        }
    }
}

extern "C" void kernel_launch(void* const* d_in, const int* in_sizes, int n_in,
                              void* d_out, int out_size) {
    const float* x    = (const float*)d_in[0];   // [8, 512, 2048]
    const float* W    = (const float*)d_in[1];   // [4096, 512]
    const float* bias = (const float*)d_in[2];   // [512]
    float* out        = (float*)d_out;           // [8, 512, 2048]

    convert_fused<<<WBLOCKS + (LLEN / 32) * (CIN / 32) * BATCH, 256>>>(W, x);

    cudaFuncSetAttribute(fold_convT_mma,
                         cudaFuncAttributeMaxDynamicSharedMemorySize, SMEM_TOTAL);
    dim3 grid(LLEN / TN, COUT / TM, BATCH / 2);  // (16, 4, 4) = 256 CTAs
    fold_convT_mma<<<grid, NTHREADS, SMEM_TOTAL>>>(bias, out);
}

// round 16
// speedup vs baseline: 7.7795x; 1.0016x over previous
#include <cuda_runtime.h>
#include <cuda_fp16.h>
#include <cstdint>

// FoldTemporalConvTranspose1d via fp16 mma.sync HMMA GEMM.
//   y[b,co,l] = bias[co] + sum_{k=0..7} sum_c W[k*512+co,c] * x[b,c,l-k]
// R15: occupancy-2 (256-thread CTAs, 105.7KB smem) so a co-resident CTA
// hides barrier/wait bubbles and 512 CTAs schedule at ~1.73 waves.
// W via 4-stage cp.async.bulk; strip via cp.async with tap-4 prefetch.

#define CIN   512
#define COUT  512
#define LLEN  2048
#define BATCH 8
#define KW    8
#define TM    128
#define TN    128
#define KC    64
#define NCHUNK (CIN / KC)   // 8
#define NIT   (NCHUNK * KW) // 64
#define SR    136           // strip rows
#define PS    72            // strip smem row stride (fp16 units, 144 B)
#define NTHREADS 256

#define TILE_ELE   (128 * 64)        // one W tile (co x c), fp16
#define TILE_BYTES (TILE_ELE * 2)    // 16384
#define NSTAGE_W   4

// smem layout (bytes, dynamic)
#define SM_MBAR 0                    // 4 mbarriers (32 B)
#define SW_BASE 1024                 // W stages: 4 x 16384 = 65536
#define SB_BASE (SW_BASE + NSTAGE_W * TILE_BYTES)   // 66560
#define SB_ONE  19584                // one strip: 136 * 72 * 2
#define SMEM_TOTAL (SB_BASE + 2 * SB_ONE)           // 105728 -> occ 2

// ---------------- scratch (static device globals; allocation-free) ----------
__device__ __align__(16) __half g_Wt[NCHUNK * KW * 4 * TILE_ELE];   // 4 MB
__device__ __align__(16) __half g_xf[BATCH * LLEN * CIN];           // 16 MB [b][l][c]

// ---------------- helpers ----------------------------------------------------
__device__ __forceinline__ uint32_t smem_u32(const void* p) {
    uint32_t a;
    asm("{ .reg .u64 t; cvta.to.shared.u64 t, %1; cvt.u32.u64 %0, t; }"
        : "=r"(a) : "l"(p));
    return a;
}
__device__ __forceinline__ void ldmatrix_x4(uint32_t* r, uint32_t addr) {
    asm volatile("ldmatrix.sync.aligned.m8n8.x4.shared.b16 {%0,%1,%2,%3}, [%4];"
                 : "=r"(r[0]), "=r"(r[1]), "=r"(r[2]), "=r"(r[3]) : "r"(addr));
}
__device__ __forceinline__ void mma16816(float* d, const uint32_t* a,
                                         uint32_t b0, uint32_t b1) {
    asm volatile(
        "mma.sync.aligned.m16n8k16.row.col.f32.f16.f16.f32 "
        "{%0,%1,%2,%3}, {%4,%5,%6,%7}, {%8,%9}, {%0,%1,%2,%3};"
        : "+f"(d[0]), "+f"(d[1]), "+f"(d[2]), "+f"(d[3])
        : "r"(a[0]), "r"(a[1]), "r"(a[2]), "r"(a[3]), "r"(b0), "r"(b1));
}
__device__ __forceinline__ void cpa16z(uint32_t dst, const void* src, bool p) {
    int sz = p ? 16 : 0;
    asm volatile(
        "{ .reg .u64 g; cvta.to.global.u64 g, %1;"
        " cp.async.cg.shared.global [%0], [g], 16, %2; }"
        :: "r"(dst), "l"(src), "r"(sz) : "memory");
}
__device__ __forceinline__ void cpa_commit() {
    asm volatile("cp.async.commit_group;" ::: "memory");
}
template <int N>
__device__ __forceinline__ void cpa_wait() {
    asm volatile("cp.async.wait_group %0;" :: "n"(N) : "memory");
}
__device__ __forceinline__ void bulk_ld(uint32_t dst, const void* src,
                                        uint32_t bytes, uint32_t mbar) {
    asm volatile(
        "{ .reg .u64 g; cvta.to.global.u64 g, %1;"
        " cp.async.bulk.shared::cluster.global.mbarrier::complete_tx::bytes"
        " [%0], [g], %2, [%3]; }"
        :: "r"(dst), "l"(src), "r"(bytes), "r"(mbar) : "memory");
}
#define MBAR_INIT(a, c) \
    asm volatile("mbarrier.init.shared.b64 [%0], %1;" :: "r"(a), "r"(c) : "memory")
#define MBAR_EXPECT_TX(a, n) \
    asm volatile("mbarrier.arrive.expect_tx.shared.b64 _, [%0], %1;" \
                 :: "r"(a), "r"(n) : "memory")
#define MBAR_WAIT(a, ph) do {                                                     \
    uint32_t _m = (a), _p = (ph), _d;                                             \
    asm volatile("{ .reg .pred p;"                                                \
        "mbarrier.try_wait.parity.acquire.cta.shared::cta.b64 p, [%1], %2;"       \
        "selp.b32 %0,1,0,p; }" : "=r"(_d) : "r"(_m), "r"(_p) : "memory");         \
    if (!_d) {                                                                    \
        asm volatile("{ .reg .pred P1; WL_%=:"                                    \
            "mbarrier.try_wait.parity.acquire.cta.shared::cta.b64 P1, [%0], %1, 0x989680;" \
            "@P1 bra.uni WD_%=; bra.uni WL_%=; WD_%=: }"                          \
            :: "r"(_m), "r"(_p) : "memory");                                      \
    }                                                                             \
} while (0)

__device__ __forceinline__ uint32_t pack2h(__half a, __half b) {
    uint16_t ua = *reinterpret_cast<uint16_t*>(&a);
    uint16_t ub = *reinterpret_cast<uint16_t*>(&b);
    return (uint32_t)ua | ((uint32_t)ub << 16);
}

// ---------------- fused pre-pass: W tiling + x transpose ----------------------
#define WBLOCKS 1024
__global__ __launch_bounds__(256)
void convert_fused(const float* __restrict__ W, const float* __restrict__ x) {
    if (blockIdx.x < WBLOCKS) {
        int idx = blockIdx.x * 256 + threadIdx.x;        // 16B chunks (8 fp16)
        int rowg = idx >> 6;                              // W row (tap*512+co)
        int c8   = (idx & 63) * 8;                        // c start
        const float* src = W + (size_t)rowg * CIN + c8;
        float4 v0 = reinterpret_cast<const float4*>(src)[0];
        float4 v1 = reinterpret_cast<const float4*>(src)[1];
        uint4 o;
        o.x = pack2h(__float2half_rn(v0.x), __float2half_rn(v0.y));
        o.y = pack2h(__float2half_rn(v0.z), __float2half_rn(v0.w));
        o.z = pack2h(__float2half_rn(v1.x), __float2half_rn(v1.y));
        o.w = pack2h(__float2half_rn(v1.z), __float2half_rn(v1.w));

        int tap = rowg >> 9;
        int co  = rowg & 511;
        int cy  = co >> 7;
        int r   = co & 127;
        int ci  = c8 >> 6;
        int cc  = c8 & 63;
        size_t dst = (size_t)(((ci * KW + tap) * 4 + cy)) * TILE_ELE
                     + r * 64 + (cc ^ ((r & 7) << 3));
        *reinterpret_cast<uint4*>(g_Wt + dst) = o;
    } else {
        __shared__ float t[32][33];
        int i = blockIdx.x - WBLOCKS;          // 0 .. 8191
        const int b  = i >> 10;
        const int rem = i & 1023;
        const int cbase = (rem >> 6) * 32;
        const int lbase = (rem & 63) * 32;
        const int tx = threadIdx.x & 31;
        const int ty = threadIdx.x >> 5;
#pragma unroll
        for (int r = 0; r < 4; ++r) {
            int c = cbase + ty + r * 8;
            t[ty + r * 8][tx] = x[((size_t)b * CIN + c) * LLEN + lbase + tx];
        }
        __syncthreads();
#pragma unroll
        for (int r = 0; r < 4; ++r) {
            int l = lbase + ty + r * 8;
            float v = t[tx][ty + r * 8];
            g_xf[((size_t)b * LLEN + l) * CIN + cbase + tx] = __float2half_rn(v);
        }
    }
}

// ---------------- main GEMM ---------------------------------------------------
__global__ __launch_bounds__(NTHREADS, 2)
void fold_convT_mma(const float* __restrict__ bias, float* __restrict__ out)
{
    extern __shared__ char smem[];
    const uint32_t sbase = smem_u32(smem);

    const int tid  = threadIdx.x;
    const int lane = tid & 31;
    const int wid  = tid >> 5;           // 0..7
    const int wm   = wid >> 2;           // 0..1 -> co 64-block
    const int wn   = wid & 3;            // 0..3 -> l 32-block
    const int bb   = blockIdx.z;
    const int co0  = blockIdx.y * TM;
    const int cy   = blockIdx.y;
    const int l0   = blockIdx.x * TN;

    float acc[4][4][4];
#pragma unroll
    for (int i = 0; i < 4; ++i)
#pragma unroll
        for (int j = 0; j < 4; ++j)
#pragma unroll
            for (int q = 0; q < 4; ++q) acc[i][j][q] = 0.0f;

    // A addressing inside swizzled W tile
    const int arow_l = wm * 64 + (lane & 15);
    const int a_sv   = (arow_l & 7) << 3;
    const int a_colb = (lane >> 4) * 8;
    // B (strip) ldmatrix lane offset
    const int b_lane = ((lane & 7) + ((lane >> 4) << 3)) * PS + ((lane >> 3) & 1) * 8;

    const uint32_t mb = sbase + SM_MBAR;     // 4 mbarriers, 8 B apart

    if (tid == 0) {
#pragma unroll
        for (int s = 0; s < NSTAGE_W; ++s) MBAR_INIT(mb + s * 8, 1);
    }
    __syncthreads();

    auto issue_Wbulk = [&](int it) {
        const int st = it & 3;
        const __half* src = g_Wt + (size_t)(it * 4 + cy) * TILE_ELE;
        MBAR_EXPECT_TX(mb + st * 8, TILE_BYTES);
        bulk_ld(sbase + SW_BASE + st * TILE_BYTES, src, TILE_BYTES, mb + st * 8);
    };
    auto issue_strip = [&](int ci, int stage) {
        const int c0 = ci * KC;
#pragma unroll
        for (int e = tid; e < SR * 8; e += NTHREADS) {
            int s = e >> 3;
            int q = (e & 7) * 8;
            int l = l0 + s - 7;
            bool p = (l >= 0) && (l < LLEN);
            int lc = p ? l : 0;
            size_t o = ((size_t)bb * LLEN + lc) * CIN + c0 + q;
            cpa16z(sbase + SB_BASE + stage * SB_ONE + (s * PS + q) * 2,
                   g_xf + o, p);
        }
    };

    // ---- prologue: strip(0) + W(0..2) ----
    issue_strip(0, 0);
    cpa_commit();
    if (tid == 0) { issue_Wbulk(0); issue_Wbulk(1); issue_Wbulk(2); }

    uint32_t wph[NSTAGE_W] = {0, 0, 0, 0};

#pragma unroll 1
    for (int it = 0; it < NIT; ++it) {
        const int ci  = it >> 3;
        const int tap = it & 7;
        const int st  = it & 3;

        if (tap == 0) cpa_wait<0>();   // strip(ci) present (own thread)
        __syncthreads();               // all warps done compute(it-1)

        if (tid == 0 && it + 3 < NIT) issue_Wbulk(it + 3);
        if (tap == 4 && it + 4 < NIT) {        // prefetch next strip: 3-it slack
            issue_strip(ci + 1, (ci + 1) & 1);
            cpa_commit();
        }

        MBAR_WAIT(mb + st * 8, wph[st]);       // W tile(it); issued at it-3
        wph[st] ^= 1;

        const uint32_t sA_u = sbase + SW_BASE + st * TILE_BYTES;
        const uint32_t sB_u = sbase + SB_BASE + (ci & 1) * SB_ONE;
        const int rowOff = (wn * 32 + 7 - tap) * PS;

#pragma unroll
        for (int ks = 0; ks < 4; ++ks) {
            uint32_t B[8];
#pragma unroll
            for (int nfp = 0; nfp < 2; ++nfp) {
                uint32_t eb = (uint32_t)(b_lane + rowOff + nfp * 16 * PS
                                         + ks * 16) * 2;
                ldmatrix_x4(&B[nfp * 4], sB_u + eb);
            }

            uint32_t a[4][4];
            const int colsw = (a_colb + ks * 16) ^ a_sv;
#pragma unroll
            for (int mf = 0; mf < 4; ++mf) {
                uint32_t ab = (uint32_t)((arow_l + mf * 16) * 64 + colsw) * 2;
                ldmatrix_x4(a[mf], sA_u + ab);
            }

#pragma unroll
            for (int mf = 0; mf < 4; ++mf)
#pragma unroll
                for (int nf = 0; nf < 4; ++nf)
                    mma16816(acc[mf][nf], a[mf], B[nf * 2], B[nf * 2 + 1]);
        }
    }

    // ---- epilogue: add bias, store float2 per (row, 8-col frag) ----
    const int r  = lane >> 2;
    const int cq = (lane & 3) * 2;
#pragma unroll
    for (int mf = 0; mf < 4; ++mf) {
#pragma unroll
        for (int h2 = 0; h2 < 2; ++h2) {
            int row = co0 + wm * 64 + mf * 16 + h2 * 8 + r;
            float bv = __ldg(bias + row);
            float* orow = out + ((size_t)bb * COUT + row) * LLEN
                          + l0 + wn * 32 + cq;
#pragma unroll
            for (int nf = 0; nf < 4; ++nf) {
                float2 v;
                v.x = acc[mf][nf][h2 * 2 + 0] + bv;
                v.y = acc[mf][nf][h2 * 2 + 1] + bv;
                *reinterpret_cast<float2*>(orow + nf * 8) = v;
            }
        }
    }
}

extern "C" void kernel_launch(void* const* d_in, const int* in_sizes, int n_in,
                              void* d_out, int out_size) {
    const float* x    = (const float*)d_in[0];   // [8, 512, 2048]
    const float* W    = (const float*)d_in[1];   // [4096, 512]
    const float* bias = (const float*)d_in[2];   // [512]
    float* out        = (float*)d_out;           // [8, 512, 2048]

    convert_fused<<<WBLOCKS + (LLEN / 32) * (CIN / 32) * BATCH, 256>>>(W, x);

    cudaFuncSetAttribute(fold_convT_mma,
                         cudaFuncAttributeMaxDynamicSharedMemorySize, SMEM_TOTAL);
    dim3 grid(LLEN / TN, COUT / TM, BATCH);      // (16, 4, 8) = 512 CTAs
    fold_convT_mma<<<grid, NTHREADS, SMEM_TOTAL>>>(bias, out);
}